// round 10
// baseline (speedup 1.0000x reference)
#include <cuda_runtime.h>
#include <cuda_bf16.h>
#include <cstdint>

#define CH    512
#define FH    64
#define FW    96
#define HW    6144          // 64*96
#define KDIM  4608          // 512*9
#define NANCH 55296         // HW*9
#define NSORT 65536
#define PRE_NMS  6000
#define POST_NMS 300

typedef unsigned long long u64;
typedef unsigned int u32;

// ------------- device scratch (no allocation allowed) -------------
__device__ float g_x[CH * HW];        // conv1 output (relu), [c][n]
__device__ float4 g_boxes[NANCH];
__device__ u64   g_keys[NSORT];

// base anchors, exact per reference _base_anchors() (verified passing r9)
__constant__ float c_anch[36] = {
    -84.f,  -40.f,  99.f,  55.f,
   -176.f,  -88.f, 191.f, 103.f,
   -360.f, -184.f, 375.f, 199.f,
    -56.f,  -56.f,  71.f,  71.f,
   -120.f, -120.f, 135.f, 135.f,
   -248.f, -248.f, 263.f, 263.f,
    -36.f,  -80.f,  51.f,  95.f,
    -80.f, -168.f,  95.f, 183.f,
   -168.f, -344.f, 183.f, 359.f
};

// ------------- packed fp32x2 helpers -------------
__device__ __forceinline__ u64 ffma2(u64 a, u64 b, u64 c) {
    u64 d;
    asm("fma.rn.f32x2 %0, %1, %2, %3;" : "=l"(d) : "l"(a), "l"(b), "l"(c));
    return d;
}
__device__ __forceinline__ u64 dup2(float v) {
    u32 u = __float_as_uint(v);
    return ((u64)u << 32) | (u64)u;
}

// =====================================================================
// Kernel 1: 3x3 conv 512->512 + bias + relu (UNCHANGED from passing r9)
// =====================================================================
__global__ void __launch_bounds__(128) conv3_kernel(
        const float* __restrict__ feat,   // [512][64][96]
        const float* __restrict__ w,      // [512][4608]
        const float* __restrict__ bias) {
    __shared__ __align__(16) float As2[16][128];  // [k][2*m] duplicated pairs
    __shared__ __align__(16) float Bs [16][128];  // [k][n]

    const int tid = threadIdx.x;
    const int n0  = blockIdx.x * 128;
    const int co0 = blockIdx.y * 64;
    const int tng = tid & 15;     // 16 N-groups of 8
    const int tmg = tid >> 4;     // 8  M-groups of 8

    const int a_m  = tid >> 1;
    const int a_kq = (tid & 1) * 8;
    const float* a_src = w + (size_t)(co0 + a_m) * KDIM;

    const int nn   = tid;
    const int n    = n0 + nn;
    const int ph   = n / FW;
    const int pw   = n - ph * FW;
    int ci = 0, r = 0;

    u64 acc[8][4];
#pragma unroll
    for (int i = 0; i < 8; i++)
#pragma unroll
        for (int p = 0; p < 4; p++) acc[i][p] = 0ull;

    for (int k0 = 0; k0 < KDIM; k0 += 16) {
        float4 v0 = *(const float4*)(a_src + k0 + a_kq);
        float4 v1 = *(const float4*)(a_src + k0 + a_kq + 4);
        float bvals[16];
#pragma unroll
        for (int q = 0; q < 16; q++) {
            int rq = r;
            int dh = rq / 3 - 1;
            int dw = rq - (rq / 3) * 3 - 1;
            int hh = ph + dh, ww = pw + dw;
            float val = 0.f;
            if ((unsigned)hh < (unsigned)FH && (unsigned)ww < (unsigned)FW)
                val = feat[ci * HW + hh * FW + ww];
            bvals[q] = val;
            r++;
            if (r == 9) { r = 0; ci++; }
        }
        __syncthreads();
        *(u64*)&As2[a_kq + 0][2 * a_m] = dup2(v0.x);
        *(u64*)&As2[a_kq + 1][2 * a_m] = dup2(v0.y);
        *(u64*)&As2[a_kq + 2][2 * a_m] = dup2(v0.z);
        *(u64*)&As2[a_kq + 3][2 * a_m] = dup2(v0.w);
        *(u64*)&As2[a_kq + 4][2 * a_m] = dup2(v1.x);
        *(u64*)&As2[a_kq + 5][2 * a_m] = dup2(v1.y);
        *(u64*)&As2[a_kq + 6][2 * a_m] = dup2(v1.z);
        *(u64*)&As2[a_kq + 7][2 * a_m] = dup2(v1.w);
#pragma unroll
        for (int q = 0; q < 16; q++) Bs[q][nn] = bvals[q];
        __syncthreads();

#pragma unroll
        for (int kk = 0; kk < 16; kk++) {
            ulonglong2 aA = *(const ulonglong2*)&As2[kk][tmg * 16 + 0];
            ulonglong2 aB = *(const ulonglong2*)&As2[kk][tmg * 16 + 4];
            ulonglong2 aC = *(const ulonglong2*)&As2[kk][tmg * 16 + 8];
            ulonglong2 aD = *(const ulonglong2*)&As2[kk][tmg * 16 + 12];
            ulonglong2 b0 = *(const ulonglong2*)&Bs[kk][tng * 8];
            ulonglong2 b1 = *(const ulonglong2*)&Bs[kk][tng * 8 + 4];
            u64 a2[8] = {aA.x, aA.y, aB.x, aB.y, aC.x, aC.y, aD.x, aD.y};
            u64 b2[4] = {b0.x, b0.y, b1.x, b1.y};
#pragma unroll
            for (int i = 0; i < 8; i++)
#pragma unroll
                for (int p = 0; p < 4; p++)
                    acc[i][p] = ffma2(a2[i], b2[p], acc[i][p]);
        }
    }

#pragma unroll
    for (int i = 0; i < 8; i++) {
        int co = co0 + tmg * 8 + i;
        float bv = bias[co];
        float* dst = &g_x[(size_t)co * HW + n0 + tng * 8];
#pragma unroll
        for (int p = 0; p < 4; p++) {
            float e0 = __uint_as_float((u32)(acc[i][p] & 0xFFFFFFFFull));
            float e1 = __uint_as_float((u32)(acc[i][p] >> 32));
            float2 o;
            o.x = fmaxf(e0 + bv, 0.f);
            o.y = fmaxf(e1 + bv, 0.f);
            *(float2*)(dst + 2 * p) = o;
        }
    }
}

// =====================================================================
// Kernel 2: fused 1x1 heads + softmax + decode (UNCHANGED from r9)
// =====================================================================
__global__ void __launch_bounds__(256) head_kernel(
        const float* __restrict__ cls_w,  const float* __restrict__ cls_b,
        const float* __restrict__ bbox_w, const float* __restrict__ bbox_b,
        const float* __restrict__ im_info) {
    __shared__ float P[3][64][54];

    const int tid = threadIdx.x;
    const int nl  = tid & 63;
    const int half = tid >> 6;
    const int n = blockIdx.x * 64 + nl;
    const int cbase = half * 128;

    float acc[54];
#pragma unroll
    for (int j = 0; j < 54; j++) acc[j] = 0.f;

    for (int cb = 0; cb < 128; cb += 4) {
        int c = cbase + cb;
        float xv0 = g_x[(size_t)(c + 0) * HW + n];
        float xv1 = g_x[(size_t)(c + 1) * HW + n];
        float xv2 = g_x[(size_t)(c + 2) * HW + n];
        float xv3 = g_x[(size_t)(c + 3) * HW + n];
#pragma unroll
        for (int j = 0; j < 18; j++) {
            float4 wv = *(const float4*)(cls_w + j * CH + c);
            acc[j] += wv.x * xv0 + wv.y * xv1 + wv.z * xv2 + wv.w * xv3;
        }
#pragma unroll
        for (int j = 0; j < 36; j++) {
            float4 wv = *(const float4*)(bbox_w + j * CH + c);
            acc[18 + j] += wv.x * xv0 + wv.y * xv1 + wv.z * xv2 + wv.w * xv3;
        }
    }
    if (half > 0) {
#pragma unroll
        for (int j = 0; j < 54; j++) P[half - 1][nl][j] = acc[j];
    }
    __syncthreads();
    if (half != 0) return;

    float v[54];
#pragma unroll
    for (int j = 0; j < 54; j++) {
        float b = (j < 18) ? cls_b[j] : bbox_b[j - 18];
        v[j] = acc[j] + P[0][nl][j] + P[1][nl][j] + P[2][nl][j] + b;
    }

    const float im_h = im_info[0];
    const float im_w = im_info[1];
    const float ms   = 16.0f * im_info[2];
    const int  ph = n / FW;
    const int  pw = n - ph * FW;
    const float sx = (float)(pw * 16);
    const float sy = (float)(ph * 16);

#pragma unroll
    for (int a = 0; a < 9; a++) {
        float s0 = v[a], s1 = v[9 + a];
        float m  = fmaxf(s0, s1);
        float e0 = expf(s0 - m), e1 = expf(s1 - m);
        float score = e1 / (e0 + e1);

        float bx1 = c_anch[4 * a + 0] + sx;
        float by1 = c_anch[4 * a + 1] + sy;
        float bx2 = c_anch[4 * a + 2] + sx;
        float by2 = c_anch[4 * a + 3] + sy;
        float aw = bx2 - bx1 + 1.0f;
        float ah = by2 - by1 + 1.0f;
        float acx = bx1 + 0.5f * aw;
        float acy = by1 + 0.5f * ah;

        float d0 = v[18 + 4 * a + 0];
        float d1 = v[18 + 4 * a + 1];
        float d2 = v[18 + 4 * a + 2];
        float d3 = v[18 + 4 * a + 3];
        float cx = d0 * aw + acx;
        float cy = d1 * ah + acy;
        float pwid = expf(d2) * aw;
        float phei = expf(d3) * ah;

        float x1 = fminf(fmaxf(cx - 0.5f * pwid, 0.f), im_w - 1.0f);
        float y1 = fminf(fmaxf(cy - 0.5f * phei, 0.f), im_h - 1.0f);
        float x2 = fminf(fmaxf(cx + 0.5f * pwid, 0.f), im_w - 1.0f);
        float y2 = fminf(fmaxf(cy + 0.5f * phei, 0.f), im_h - 1.0f);

        bool keep = (x2 - x1 + 1.0f >= ms) && (y2 - y1 + 1.0f >= ms);
        float se = keep ? score : -__int_as_float(0x7F800000);  // -inf
        u32 sb = __float_as_uint(se);
        u32 mono = (sb & 0x80000000u) ? ~sb : (sb | 0x80000000u);
        int idx = n * 9 + a;
        g_keys[idx]  = ((u64)mono << 32) | (u64)(0xFFFFFFFFu - (u32)idx);
        g_boxes[idx] = make_float4(x1, y1, x2, y2);
    }
}

// ------------- pad keys [55296, 65536) with 0 (sorts last) -------------
__global__ void pad_keys_kernel() {
    int i = blockIdx.x * blockDim.x + threadIdx.x;
    if (i < NSORT - NANCH) g_keys[NANCH + i] = 0ull;
}

// =====================================================================
// Bitonic top-k: 8 chunks of 8192 sorted descending, then prune-merge
// tree keeps top-8192 (superset of top-6000), fully sorted.
// =====================================================================
__device__ __forceinline__ void cswap(u64& a, u64& b, bool dec) {
    if (dec ? (a < b) : (a > b)) { u64 t = a; a = b; b = t; }
}

// Full descending sort of one 8192-chunk in shared memory.
__global__ void __launch_bounds__(1024) sort8k_kernel() {
    extern __shared__ u64 S[];
    const int base = blockIdx.x * 8192;
    const int tid = threadIdx.x;
#pragma unroll
    for (int q = 0; q < 8; q++) S[tid + q * 1024] = g_keys[base + tid + q * 1024];
    __syncthreads();
    for (int k = 2; k <= 8192; k <<= 1) {
        for (int j = k >> 1; j > 0; j >>= 1) {
#pragma unroll
            for (int t0 = 0; t0 < 4; t0++) {
                int t = tid + t0 * 1024;                 // 0..4095 pairs
                int i = ((t & ~(j - 1)) << 1) | (t & (j - 1));
                bool dec = ((i & k) == 0);               // final k=8192 -> descending
                cswap(S[i], S[i + j], dec);
            }
            __syncthreads();
        }
    }
#pragma unroll
    for (int q = 0; q < 8; q++) g_keys[base + tid + q * 1024] = S[tid + q * 1024];
}

// Prune-merge: C[i] = max(A[i], B[8191-i]) = top-8192 of union (bitonic),
// then 13-phase descending clean. Writes to A's slot.
__global__ void __launch_bounds__(1024) merge8k_kernel(int stride) {
    extern __shared__ u64 S[];
    const int base1 = blockIdx.x * 2 * stride * 8192;
    const int base2 = base1 + stride * 8192;
    const int tid = threadIdx.x;
#pragma unroll
    for (int q = 0; q < 8; q++) {
        int i = tid + q * 1024;
        u64 a = g_keys[base1 + i];
        u64 b = g_keys[base2 + 8191 - i];
        S[i] = (a > b) ? a : b;
    }
    __syncthreads();
    for (int j = 4096; j > 0; j >>= 1) {
#pragma unroll
        for (int t0 = 0; t0 < 4; t0++) {
            int t = tid + t0 * 1024;
            int i = ((t & ~(j - 1)) << 1) | (t & (j - 1));
            cswap(S[i], S[i + j], true);
        }
        __syncthreads();
    }
#pragma unroll
    for (int q = 0; q < 8; q++) g_keys[base1 + tid + q * 1024] = S[tid + q * 1024];
}

// =====================================================================
// Greedy NMS, monotonic-pointer version. 256 threads, 24 boxes/thread
// in registers, byte flags in smem, warp-0 ballot scan for next winner.
// Sorted descending => argmax(avail) == first unsuppressed position,
// and that position is monotonically nondecreasing.
// =====================================================================
#define NMS_T   256
#define NMS_S   24            // 256*24 = 6144 slots >= 6000

__global__ void __launch_bounds__(NMS_T) nms_kernel(float* __restrict__ out) {
    const int tid = threadIdx.x;

    __shared__ unsigned char flags[NMS_T * NMS_S];   // 1 = suppressed/invalid
    __shared__ int s_win;
    __shared__ int s_ptr;
    __shared__ float4 s_box;
    __shared__ float s_area;

    float4 box[NMS_S];
    float  area[NMS_S];

#pragma unroll
    for (int s = 0; s < NMS_S; s++) {
        int p = s * NMS_T + tid;
        unsigned char f = 1;
        box[s] = make_float4(0.f, 0.f, 0.f, 0.f);
        area[s] = 0.f;
        if (p < PRE_NMS) {
            u64 key = g_keys[p];
            u32 idx = 0xFFFFFFFFu - (u32)(key & 0xFFFFFFFFull);
            float4 b = g_boxes[idx];
            box[s] = b;
            area[s] = (b.z - b.x + 1.0f) * (b.w - b.y + 1.0f);
            if ((u32)(key >> 32) > 0x007FFFFFu) f = 0;   // valid score
        }
        flags[p] = f;
    }
    if (tid == 0) s_ptr = 0;
    __syncthreads();

    for (int it = 0; it < POST_NMS; it++) {
        // warp 0: find first unsuppressed position >= s_ptr
        if (tid < 32) {
            int p = s_ptr;
            int found = -1;
            while (p < NMS_T * NMS_S) {
                int q = p + tid;
                bool freeSlot = (q < NMS_T * NMS_S) && (flags[q] == 0);
                unsigned m = __ballot_sync(0xFFFFFFFFu, freeSlot);
                if (m) { found = p + __ffs(m) - 1; break; }
                p += 32;
            }
            if (tid == 0) {
                s_win = found;
                s_ptr = (found >= 0) ? found : NMS_T * NMS_S;
            }
        }
        __syncthreads();
        int win = s_win;
        if (win >= 0 && tid == (win & (NMS_T - 1))) {
            int s = win >> 8;                 // win / NMS_T
            s_box = box[s];
            s_area = area[s];
            flags[win] = 1;                   // self-suppress
        }
        __syncthreads();

        if (tid == 0) {
            bool ok = (win >= 0);
            out[it * 5 + 0] = 0.f;
            out[it * 5 + 1] = ok ? s_box.x : 0.f;
            out[it * 5 + 2] = ok ? s_box.y : 0.f;
            out[it * 5 + 3] = ok ? s_box.z : 0.f;
            out[it * 5 + 4] = ok ? s_box.w : 0.f;
        }
        if (win >= 0) {
            float4 B = s_box;
            float A = s_area;
#pragma unroll
            for (int s = 0; s < NMS_S; s++) {
                int p2 = s * NMS_T + tid;
                if (flags[p2] == 0) {
                    float xx1 = fmaxf(B.x, box[s].x);
                    float yy1 = fmaxf(B.y, box[s].y);
                    float xx2 = fminf(B.z, box[s].z);
                    float yy2 = fminf(B.w, box[s].w);
                    float inter = fmaxf(xx2 - xx1 + 1.0f, 0.f) *
                                  fmaxf(yy2 - yy1 + 1.0f, 0.f);
                    float iou = inter / (A + area[s] - inter);
                    if (iou > 0.7f) flags[p2] = 1;
                }
            }
        }
        __syncthreads();
    }
}

// =====================================================================
extern "C" void kernel_launch(void* const* d_in, const int* in_sizes, int n_in,
                              void* d_out, int out_size) {
    // Bind inputs by UNIQUE element count — robust to metadata ordering.
    const float *feat = 0, *im_info = 0, *conv_w = 0, *conv_b = 0;
    const float *cls_w = 0, *cls_b = 0, *bbox_w = 0, *bbox_b = 0;
    for (int i = 0; i < n_in; i++) {
        const float* p = (const float*)d_in[i];
        switch (in_sizes[i]) {
            case 3145728: feat    = p; break;
            case 3:       im_info = p; break;
            case 2359296: conv_w  = p; break;
            case 512:     conv_b  = p; break;
            case 9216:    cls_w   = p; break;
            case 18:      cls_b   = p; break;
            case 18432:   bbox_w  = p; break;
            case 36:      bbox_b  = p; break;
            default: break;
        }
    }
    if (!feat || !im_info || !conv_w || !conv_b || !cls_w || !cls_b || !bbox_w || !bbox_b) {
        feat    = (const float*)d_in[0];
        im_info = (const float*)d_in[1];
        conv_w  = (const float*)d_in[2];
        conv_b  = (const float*)d_in[3];
        cls_w   = (const float*)d_in[4];
        cls_b   = (const float*)d_in[5];
        bbox_w  = (const float*)d_in[6];
        bbox_b  = (const float*)d_in[7];
    }
    float* out = (float*)d_out;

    // 64KB dynamic smem opt-in (idempotent; not a stream op, capture-safe)
    cudaFuncSetAttribute(sort8k_kernel,
                         cudaFuncAttributeMaxDynamicSharedMemorySize, 65536);
    cudaFuncSetAttribute(merge8k_kernel,
                         cudaFuncAttributeMaxDynamicSharedMemorySize, 65536);

    conv3_kernel<<<dim3(HW / 128, CH / 64), 128>>>(feat, conv_w, conv_b);
    head_kernel<<<HW / 64, 256>>>(cls_w, cls_b, bbox_w, bbox_b, im_info);
    pad_keys_kernel<<<(NSORT - NANCH + 255) / 256, 256>>>();

    sort8k_kernel<<<8, 1024, 65536>>>();
    merge8k_kernel<<<4, 1024, 65536>>>(1);
    merge8k_kernel<<<2, 1024, 65536>>>(2);
    merge8k_kernel<<<1, 1024, 65536>>>(4);

    nms_kernel<<<1, NMS_T>>>(out);
}

// round 11
// speedup vs baseline: 1.5112x; 1.5112x over previous
#include <cuda_runtime.h>
#include <cuda_bf16.h>
#include <cstdint>

#define CH    512
#define FH    64
#define FW    96
#define HW    6144          // 64*96
#define KDIM  4608          // 512*9
#define NANCH 55296         // HW*9
#define NSORT 65536
#define PRE_NMS  6000
#define POST_NMS 300

typedef unsigned long long u64;
typedef unsigned int u32;

// ------------- device scratch (no allocation allowed) -------------
__device__ float g_x[CH * HW];        // conv1 output (relu), [c][n]
__device__ float4 g_boxes[NANCH];
__device__ u64   g_keys[NSORT];

// base anchors, exact per reference _base_anchors() (verified passing r9)
__constant__ float c_anch[36] = {
    -84.f,  -40.f,  99.f,  55.f,
   -176.f,  -88.f, 191.f, 103.f,
   -360.f, -184.f, 375.f, 199.f,
    -56.f,  -56.f,  71.f,  71.f,
   -120.f, -120.f, 135.f, 135.f,
   -248.f, -248.f, 263.f, 263.f,
    -36.f,  -80.f,  51.f,  95.f,
    -80.f, -168.f,  95.f, 183.f,
   -168.f, -344.f, 183.f, 359.f
};

// ------------- packed fp32x2 helpers -------------
__device__ __forceinline__ u64 ffma2(u64 a, u64 b, u64 c) {
    u64 d;
    asm("fma.rn.f32x2 %0, %1, %2, %3;" : "=l"(d) : "l"(a), "l"(b), "l"(c));
    return d;
}
__device__ __forceinline__ u64 dup2(float v) {
    u32 u = __float_as_uint(v);
    return ((u64)u << 32) | (u64)u;
}

// =====================================================================
// Kernel 1: 3x3 conv 512->512 + bias + relu (UNCHANGED from passing r9)
// =====================================================================
__global__ void __launch_bounds__(128) conv3_kernel(
        const float* __restrict__ feat,   // [512][64][96]
        const float* __restrict__ w,      // [512][4608]
        const float* __restrict__ bias) {
    __shared__ __align__(16) float As2[16][128];  // [k][2*m] duplicated pairs
    __shared__ __align__(16) float Bs [16][128];  // [k][n]

    const int tid = threadIdx.x;
    const int n0  = blockIdx.x * 128;
    const int co0 = blockIdx.y * 64;
    const int tng = tid & 15;     // 16 N-groups of 8
    const int tmg = tid >> 4;     // 8  M-groups of 8

    const int a_m  = tid >> 1;
    const int a_kq = (tid & 1) * 8;
    const float* a_src = w + (size_t)(co0 + a_m) * KDIM;

    const int nn   = tid;
    const int n    = n0 + nn;
    const int ph   = n / FW;
    const int pw   = n - ph * FW;
    int ci = 0, r = 0;

    u64 acc[8][4];
#pragma unroll
    for (int i = 0; i < 8; i++)
#pragma unroll
        for (int p = 0; p < 4; p++) acc[i][p] = 0ull;

    for (int k0 = 0; k0 < KDIM; k0 += 16) {
        float4 v0 = *(const float4*)(a_src + k0 + a_kq);
        float4 v1 = *(const float4*)(a_src + k0 + a_kq + 4);
        float bvals[16];
#pragma unroll
        for (int q = 0; q < 16; q++) {
            int rq = r;
            int dh = rq / 3 - 1;
            int dw = rq - (rq / 3) * 3 - 1;
            int hh = ph + dh, ww = pw + dw;
            float val = 0.f;
            if ((unsigned)hh < (unsigned)FH && (unsigned)ww < (unsigned)FW)
                val = feat[ci * HW + hh * FW + ww];
            bvals[q] = val;
            r++;
            if (r == 9) { r = 0; ci++; }
        }
        __syncthreads();
        *(u64*)&As2[a_kq + 0][2 * a_m] = dup2(v0.x);
        *(u64*)&As2[a_kq + 1][2 * a_m] = dup2(v0.y);
        *(u64*)&As2[a_kq + 2][2 * a_m] = dup2(v0.z);
        *(u64*)&As2[a_kq + 3][2 * a_m] = dup2(v0.w);
        *(u64*)&As2[a_kq + 4][2 * a_m] = dup2(v1.x);
        *(u64*)&As2[a_kq + 5][2 * a_m] = dup2(v1.y);
        *(u64*)&As2[a_kq + 6][2 * a_m] = dup2(v1.z);
        *(u64*)&As2[a_kq + 7][2 * a_m] = dup2(v1.w);
#pragma unroll
        for (int q = 0; q < 16; q++) Bs[q][nn] = bvals[q];
        __syncthreads();

#pragma unroll
        for (int kk = 0; kk < 16; kk++) {
            ulonglong2 aA = *(const ulonglong2*)&As2[kk][tmg * 16 + 0];
            ulonglong2 aB = *(const ulonglong2*)&As2[kk][tmg * 16 + 4];
            ulonglong2 aC = *(const ulonglong2*)&As2[kk][tmg * 16 + 8];
            ulonglong2 aD = *(const ulonglong2*)&As2[kk][tmg * 16 + 12];
            ulonglong2 b0 = *(const ulonglong2*)&Bs[kk][tng * 8];
            ulonglong2 b1 = *(const ulonglong2*)&Bs[kk][tng * 8 + 4];
            u64 a2[8] = {aA.x, aA.y, aB.x, aB.y, aC.x, aC.y, aD.x, aD.y};
            u64 b2[4] = {b0.x, b0.y, b1.x, b1.y};
#pragma unroll
            for (int i = 0; i < 8; i++)
#pragma unroll
                for (int p = 0; p < 4; p++)
                    acc[i][p] = ffma2(a2[i], b2[p], acc[i][p]);
        }
    }

#pragma unroll
    for (int i = 0; i < 8; i++) {
        int co = co0 + tmg * 8 + i;
        float bv = bias[co];
        float* dst = &g_x[(size_t)co * HW + n0 + tng * 8];
#pragma unroll
        for (int p = 0; p < 4; p++) {
            float e0 = __uint_as_float((u32)(acc[i][p] & 0xFFFFFFFFull));
            float e1 = __uint_as_float((u32)(acc[i][p] >> 32));
            float2 o;
            o.x = fmaxf(e0 + bv, 0.f);
            o.y = fmaxf(e1 + bv, 0.f);
            *(float2*)(dst + 2 * p) = o;
        }
    }
}

// =====================================================================
// Kernel 2: fused 1x1 heads + softmax + decode (UNCHANGED from r9)
// =====================================================================
__global__ void __launch_bounds__(256) head_kernel(
        const float* __restrict__ cls_w,  const float* __restrict__ cls_b,
        const float* __restrict__ bbox_w, const float* __restrict__ bbox_b,
        const float* __restrict__ im_info) {
    __shared__ float P[3][64][54];

    const int tid = threadIdx.x;
    const int nl  = tid & 63;
    const int half = tid >> 6;
    const int n = blockIdx.x * 64 + nl;
    const int cbase = half * 128;

    float acc[54];
#pragma unroll
    for (int j = 0; j < 54; j++) acc[j] = 0.f;

    for (int cb = 0; cb < 128; cb += 4) {
        int c = cbase + cb;
        float xv0 = g_x[(size_t)(c + 0) * HW + n];
        float xv1 = g_x[(size_t)(c + 1) * HW + n];
        float xv2 = g_x[(size_t)(c + 2) * HW + n];
        float xv3 = g_x[(size_t)(c + 3) * HW + n];
#pragma unroll
        for (int j = 0; j < 18; j++) {
            float4 wv = *(const float4*)(cls_w + j * CH + c);
            acc[j] += wv.x * xv0 + wv.y * xv1 + wv.z * xv2 + wv.w * xv3;
        }
#pragma unroll
        for (int j = 0; j < 36; j++) {
            float4 wv = *(const float4*)(bbox_w + j * CH + c);
            acc[18 + j] += wv.x * xv0 + wv.y * xv1 + wv.z * xv2 + wv.w * xv3;
        }
    }
    if (half > 0) {
#pragma unroll
        for (int j = 0; j < 54; j++) P[half - 1][nl][j] = acc[j];
    }
    __syncthreads();
    if (half != 0) return;

    float v[54];
#pragma unroll
    for (int j = 0; j < 54; j++) {
        float b = (j < 18) ? cls_b[j] : bbox_b[j - 18];
        v[j] = acc[j] + P[0][nl][j] + P[1][nl][j] + P[2][nl][j] + b;
    }

    const float im_h = im_info[0];
    const float im_w = im_info[1];
    const float ms   = 16.0f * im_info[2];
    const int  ph = n / FW;
    const int  pw = n - ph * FW;
    const float sx = (float)(pw * 16);
    const float sy = (float)(ph * 16);

#pragma unroll
    for (int a = 0; a < 9; a++) {
        float s0 = v[a], s1 = v[9 + a];
        float m  = fmaxf(s0, s1);
        float e0 = expf(s0 - m), e1 = expf(s1 - m);
        float score = e1 / (e0 + e1);

        float bx1 = c_anch[4 * a + 0] + sx;
        float by1 = c_anch[4 * a + 1] + sy;
        float bx2 = c_anch[4 * a + 2] + sx;
        float by2 = c_anch[4 * a + 3] + sy;
        float aw = bx2 - bx1 + 1.0f;
        float ah = by2 - by1 + 1.0f;
        float acx = bx1 + 0.5f * aw;
        float acy = by1 + 0.5f * ah;

        float d0 = v[18 + 4 * a + 0];
        float d1 = v[18 + 4 * a + 1];
        float d2 = v[18 + 4 * a + 2];
        float d3 = v[18 + 4 * a + 3];
        float cx = d0 * aw + acx;
        float cy = d1 * ah + acy;
        float pwid = expf(d2) * aw;
        float phei = expf(d3) * ah;

        float x1 = fminf(fmaxf(cx - 0.5f * pwid, 0.f), im_w - 1.0f);
        float y1 = fminf(fmaxf(cy - 0.5f * phei, 0.f), im_h - 1.0f);
        float x2 = fminf(fmaxf(cx + 0.5f * pwid, 0.f), im_w - 1.0f);
        float y2 = fminf(fmaxf(cy + 0.5f * phei, 0.f), im_h - 1.0f);

        bool keep = (x2 - x1 + 1.0f >= ms) && (y2 - y1 + 1.0f >= ms);
        float se = keep ? score : -__int_as_float(0x7F800000);  // -inf
        u32 sb = __float_as_uint(se);
        u32 mono = (sb & 0x80000000u) ? ~sb : (sb | 0x80000000u);
        int idx = n * 9 + a;
        g_keys[idx]  = ((u64)mono << 32) | (u64)(0xFFFFFFFFu - (u32)idx);
        g_boxes[idx] = make_float4(x1, y1, x2, y2);
    }
}

// ------------- pad keys [55296, 65536) with 0 (sorts last) -------------
__global__ void pad_keys_kernel() {
    int i = blockIdx.x * blockDim.x + threadIdx.x;
    if (i < NSORT - NANCH) g_keys[NANCH + i] = 0ull;
}

// =====================================================================
// Bitonic top-k (UNCHANGED from r10, measured ~240us total):
// 8 chunks of 8192 sorted descending, then prune-merge tree keeps
// top-8192 (superset of top-6000), fully sorted.
// =====================================================================
__device__ __forceinline__ void cswap(u64& a, u64& b, bool dec) {
    if (dec ? (a < b) : (a > b)) { u64 t = a; a = b; b = t; }
}

__global__ void __launch_bounds__(1024) sort8k_kernel() {
    extern __shared__ u64 S[];
    const int base = blockIdx.x * 8192;
    const int tid = threadIdx.x;
#pragma unroll
    for (int q = 0; q < 8; q++) S[tid + q * 1024] = g_keys[base + tid + q * 1024];
    __syncthreads();
    for (int k = 2; k <= 8192; k <<= 1) {
        for (int j = k >> 1; j > 0; j >>= 1) {
#pragma unroll
            for (int t0 = 0; t0 < 4; t0++) {
                int t = tid + t0 * 1024;                 // 0..4095 pairs
                int i = ((t & ~(j - 1)) << 1) | (t & (j - 1));
                bool dec = ((i & k) == 0);               // final k=8192 -> descending
                cswap(S[i], S[i + j], dec);
            }
            __syncthreads();
        }
    }
#pragma unroll
    for (int q = 0; q < 8; q++) g_keys[base + tid + q * 1024] = S[tid + q * 1024];
}

__global__ void __launch_bounds__(1024) merge8k_kernel(int stride) {
    extern __shared__ u64 S[];
    const int base1 = blockIdx.x * 2 * stride * 8192;
    const int base2 = base1 + stride * 8192;
    const int tid = threadIdx.x;
#pragma unroll
    for (int q = 0; q < 8; q++) {
        int i = tid + q * 1024;
        u64 a = g_keys[base1 + i];
        u64 b = g_keys[base2 + 8191 - i];
        S[i] = (a > b) ? a : b;
    }
    __syncthreads();
    for (int j = 4096; j > 0; j >>= 1) {
#pragma unroll
        for (int t0 = 0; t0 < 4; t0++) {
            int t = tid + t0 * 1024;
            int i = ((t & ~(j - 1)) << 1) | (t & (j - 1));
            cswap(S[i], S[i + j], true);
        }
        __syncthreads();
    }
#pragma unroll
    for (int q = 0; q < 8; q++) g_keys[base1 + tid + q * 1024] = S[tid + q * 1024];
}

// =====================================================================
// Greedy NMS: 1024 threads x 6 REGISTER slots (no spill, r9 layout)
// + monotonic-pointer ballot scan for selection (r10 idea).
// Sorted descending => greedy argmax == first unsuppressed position,
// which is monotonically nondecreasing across iterations.
// =====================================================================
#define NMS_T 1024
#define NMS_S 6               // 1024*6 = 6144 slots >= 6000

__global__ void __launch_bounds__(NMS_T) nms_kernel(float* __restrict__ out) {
    const int tid = threadIdx.x;

    __shared__ unsigned char flags[NMS_T * NMS_S];   // 1 = suppressed/invalid
    __shared__ int s_win;
    __shared__ int s_ptr;
    __shared__ float4 s_box;
    __shared__ float s_area;

    float4 box[NMS_S];
    float  area[NMS_S];

#pragma unroll
    for (int s = 0; s < NMS_S; s++) {
        int p = s * NMS_T + tid;
        unsigned char f = 1;
        box[s] = make_float4(0.f, 0.f, 0.f, 0.f);
        area[s] = 0.f;
        if (p < PRE_NMS) {
            u64 key = g_keys[p];
            u32 idx = 0xFFFFFFFFu - (u32)(key & 0xFFFFFFFFull);
            float4 b = g_boxes[idx];
            box[s] = b;
            area[s] = (b.z - b.x + 1.0f) * (b.w - b.y + 1.0f);
            if ((u32)(key >> 32) > 0x007FFFFFu) f = 0;   // valid score
        }
        flags[p] = f;
    }
    if (tid == 0) s_ptr = 0;
    __syncthreads();

    for (int it = 0; it < POST_NMS; it++) {
        // warp 0: find first unsuppressed position >= s_ptr (monotonic)
        if (tid < 32) {
            int p = s_ptr;
            int found = -1;
            while (p < NMS_T * NMS_S) {
                int q = p + tid;
                bool freeSlot = (q < NMS_T * NMS_S) && (flags[q] == 0);
                unsigned m = __ballot_sync(0xFFFFFFFFu, freeSlot);
                if (m) { found = p + __ffs(m) - 1; break; }
                p += 32;
            }
            if (tid == 0) {
                s_win = found;
                s_ptr = (found >= 0) ? found : NMS_T * NMS_S;
            }
        }
        __syncthreads();
        int win = s_win;
        if (win >= 0 && tid == (win & (NMS_T - 1))) {
            int s = win >> 10;                // win / NMS_T
            s_box = box[s];
            s_area = area[s];
            flags[win] = 1;                   // self-suppress
        }
        __syncthreads();

        if (tid == 0) {
            bool ok = (win >= 0);
            out[it * 5 + 0] = 0.f;
            out[it * 5 + 1] = ok ? s_box.x : 0.f;
            out[it * 5 + 2] = ok ? s_box.y : 0.f;
            out[it * 5 + 3] = ok ? s_box.z : 0.f;
            out[it * 5 + 4] = ok ? s_box.w : 0.f;
        }
        if (win >= 0) {
            float4 B = s_box;
            float A = s_area;
#pragma unroll
            for (int s = 0; s < NMS_S; s++) {
                int p2 = s * NMS_T + tid;
                if (flags[p2] == 0) {
                    float xx1 = fmaxf(B.x, box[s].x);
                    float yy1 = fmaxf(B.y, box[s].y);
                    float xx2 = fminf(B.z, box[s].z);
                    float yy2 = fminf(B.w, box[s].w);
                    float inter = fmaxf(xx2 - xx1 + 1.0f, 0.f) *
                                  fmaxf(yy2 - yy1 + 1.0f, 0.f);
                    float iou = inter / (A + area[s] - inter);
                    if (iou > 0.7f) flags[p2] = 1;
                }
            }
        }
        __syncthreads();
    }
}

// =====================================================================
extern "C" void kernel_launch(void* const* d_in, const int* in_sizes, int n_in,
                              void* d_out, int out_size) {
    // Bind inputs by UNIQUE element count — robust to metadata ordering.
    const float *feat = 0, *im_info = 0, *conv_w = 0, *conv_b = 0;
    const float *cls_w = 0, *cls_b = 0, *bbox_w = 0, *bbox_b = 0;
    for (int i = 0; i < n_in; i++) {
        const float* p = (const float*)d_in[i];
        switch (in_sizes[i]) {
            case 3145728: feat    = p; break;
            case 3:       im_info = p; break;
            case 2359296: conv_w  = p; break;
            case 512:     conv_b  = p; break;
            case 9216:    cls_w   = p; break;
            case 18:      cls_b   = p; break;
            case 18432:   bbox_w  = p; break;
            case 36:      bbox_b  = p; break;
            default: break;
        }
    }
    if (!feat || !im_info || !conv_w || !conv_b || !cls_w || !cls_b || !bbox_w || !bbox_b) {
        feat    = (const float*)d_in[0];
        im_info = (const float*)d_in[1];
        conv_w  = (const float*)d_in[2];
        conv_b  = (const float*)d_in[3];
        cls_w   = (const float*)d_in[4];
        cls_b   = (const float*)d_in[5];
        bbox_w  = (const float*)d_in[6];
        bbox_b  = (const float*)d_in[7];
    }
    float* out = (float*)d_out;

    cudaFuncSetAttribute(sort8k_kernel,
                         cudaFuncAttributeMaxDynamicSharedMemorySize, 65536);
    cudaFuncSetAttribute(merge8k_kernel,
                         cudaFuncAttributeMaxDynamicSharedMemorySize, 65536);

    conv3_kernel<<<dim3(HW / 128, CH / 64), 128>>>(feat, conv_w, conv_b);
    head_kernel<<<HW / 64, 256>>>(cls_w, cls_b, bbox_w, bbox_b, im_info);
    pad_keys_kernel<<<(NSORT - NANCH + 255) / 256, 256>>>();

    sort8k_kernel<<<8, 1024, 65536>>>();
    merge8k_kernel<<<4, 1024, 65536>>>(1);
    merge8k_kernel<<<2, 1024, 65536>>>(2);
    merge8k_kernel<<<1, 1024, 65536>>>(4);

    nms_kernel<<<1, NMS_T>>>(out);
}

// round 12
// speedup vs baseline: 1.5603x; 1.0325x over previous
#include <cuda_runtime.h>
#include <cuda_bf16.h>
#include <cstdint>

#define CH    512
#define FH    64
#define FW    96
#define HW    6144          // 64*96
#define KDIM  4608          // 512*9
#define NANCH 55296         // HW*9
#define NSORT 65536
#define PRE_NMS  6000
#define POST_NMS 300

typedef unsigned long long u64;
typedef unsigned int u32;

// ------------- device scratch (no allocation allowed) -------------
__device__ float g_x[CH * HW];        // conv1 output (relu), [c][n]
__device__ float4 g_boxes[NANCH];
__device__ u64   g_keys[NSORT];

// base anchors, exact per reference _base_anchors() (verified passing r9)
__constant__ float c_anch[36] = {
    -84.f,  -40.f,  99.f,  55.f,
   -176.f,  -88.f, 191.f, 103.f,
   -360.f, -184.f, 375.f, 199.f,
    -56.f,  -56.f,  71.f,  71.f,
   -120.f, -120.f, 135.f, 135.f,
   -248.f, -248.f, 263.f, 263.f,
    -36.f,  -80.f,  51.f,  95.f,
    -80.f, -168.f,  95.f, 183.f,
   -168.f, -344.f, 183.f, 359.f
};

// ------------- packed fp32x2 helpers -------------
__device__ __forceinline__ u64 ffma2(u64 a, u64 b, u64 c) {
    u64 d;
    asm("fma.rn.f32x2 %0, %1, %2, %3;" : "=l"(d) : "l"(a), "l"(b), "l"(c));
    return d;
}
__device__ __forceinline__ u64 dup2(float v) {
    u32 u = __float_as_uint(v);
    return ((u64)u << 32) | (u64)u;
}

// =====================================================================
// Kernel 1: 3x3 conv 512->512 + bias + relu (UNCHANGED from passing r9)
// =====================================================================
__global__ void __launch_bounds__(128) conv3_kernel(
        const float* __restrict__ feat,   // [512][64][96]
        const float* __restrict__ w,      // [512][4608]
        const float* __restrict__ bias) {
    __shared__ __align__(16) float As2[16][128];  // [k][2*m] duplicated pairs
    __shared__ __align__(16) float Bs [16][128];  // [k][n]

    const int tid = threadIdx.x;
    const int n0  = blockIdx.x * 128;
    const int co0 = blockIdx.y * 64;
    const int tng = tid & 15;     // 16 N-groups of 8
    const int tmg = tid >> 4;     // 8  M-groups of 8

    const int a_m  = tid >> 1;
    const int a_kq = (tid & 1) * 8;
    const float* a_src = w + (size_t)(co0 + a_m) * KDIM;

    const int nn   = tid;
    const int n    = n0 + nn;
    const int ph   = n / FW;
    const int pw   = n - ph * FW;
    int ci = 0, r = 0;

    u64 acc[8][4];
#pragma unroll
    for (int i = 0; i < 8; i++)
#pragma unroll
        for (int p = 0; p < 4; p++) acc[i][p] = 0ull;

    for (int k0 = 0; k0 < KDIM; k0 += 16) {
        float4 v0 = *(const float4*)(a_src + k0 + a_kq);
        float4 v1 = *(const float4*)(a_src + k0 + a_kq + 4);
        float bvals[16];
#pragma unroll
        for (int q = 0; q < 16; q++) {
            int rq = r;
            int dh = rq / 3 - 1;
            int dw = rq - (rq / 3) * 3 - 1;
            int hh = ph + dh, ww = pw + dw;
            float val = 0.f;
            if ((unsigned)hh < (unsigned)FH && (unsigned)ww < (unsigned)FW)
                val = feat[ci * HW + hh * FW + ww];
            bvals[q] = val;
            r++;
            if (r == 9) { r = 0; ci++; }
        }
        __syncthreads();
        *(u64*)&As2[a_kq + 0][2 * a_m] = dup2(v0.x);
        *(u64*)&As2[a_kq + 1][2 * a_m] = dup2(v0.y);
        *(u64*)&As2[a_kq + 2][2 * a_m] = dup2(v0.z);
        *(u64*)&As2[a_kq + 3][2 * a_m] = dup2(v0.w);
        *(u64*)&As2[a_kq + 4][2 * a_m] = dup2(v1.x);
        *(u64*)&As2[a_kq + 5][2 * a_m] = dup2(v1.y);
        *(u64*)&As2[a_kq + 6][2 * a_m] = dup2(v1.z);
        *(u64*)&As2[a_kq + 7][2 * a_m] = dup2(v1.w);
#pragma unroll
        for (int q = 0; q < 16; q++) Bs[q][nn] = bvals[q];
        __syncthreads();

#pragma unroll
        for (int kk = 0; kk < 16; kk++) {
            ulonglong2 aA = *(const ulonglong2*)&As2[kk][tmg * 16 + 0];
            ulonglong2 aB = *(const ulonglong2*)&As2[kk][tmg * 16 + 4];
            ulonglong2 aC = *(const ulonglong2*)&As2[kk][tmg * 16 + 8];
            ulonglong2 aD = *(const ulonglong2*)&As2[kk][tmg * 16 + 12];
            ulonglong2 b0 = *(const ulonglong2*)&Bs[kk][tng * 8];
            ulonglong2 b1 = *(const ulonglong2*)&Bs[kk][tng * 8 + 4];
            u64 a2[8] = {aA.x, aA.y, aB.x, aB.y, aC.x, aC.y, aD.x, aD.y};
            u64 b2[4] = {b0.x, b0.y, b1.x, b1.y};
#pragma unroll
            for (int i = 0; i < 8; i++)
#pragma unroll
                for (int p = 0; p < 4; p++)
                    acc[i][p] = ffma2(a2[i], b2[p], acc[i][p]);
        }
    }

#pragma unroll
    for (int i = 0; i < 8; i++) {
        int co = co0 + tmg * 8 + i;
        float bv = bias[co];
        float* dst = &g_x[(size_t)co * HW + n0 + tng * 8];
#pragma unroll
        for (int p = 0; p < 4; p++) {
            float e0 = __uint_as_float((u32)(acc[i][p] & 0xFFFFFFFFull));
            float e1 = __uint_as_float((u32)(acc[i][p] >> 32));
            float2 o;
            o.x = fmaxf(e0 + bv, 0.f);
            o.y = fmaxf(e1 + bv, 0.f);
            *(float2*)(dst + 2 * p) = o;
        }
    }
}

// =====================================================================
// Kernel 2: fused 1x1 heads + softmax + decode (UNCHANGED from r9)
// =====================================================================
__global__ void __launch_bounds__(256) head_kernel(
        const float* __restrict__ cls_w,  const float* __restrict__ cls_b,
        const float* __restrict__ bbox_w, const float* __restrict__ bbox_b,
        const float* __restrict__ im_info) {
    __shared__ float P[3][64][54];

    const int tid = threadIdx.x;
    const int nl  = tid & 63;
    const int half = tid >> 6;
    const int n = blockIdx.x * 64 + nl;
    const int cbase = half * 128;

    float acc[54];
#pragma unroll
    for (int j = 0; j < 54; j++) acc[j] = 0.f;

    for (int cb = 0; cb < 128; cb += 4) {
        int c = cbase + cb;
        float xv0 = g_x[(size_t)(c + 0) * HW + n];
        float xv1 = g_x[(size_t)(c + 1) * HW + n];
        float xv2 = g_x[(size_t)(c + 2) * HW + n];
        float xv3 = g_x[(size_t)(c + 3) * HW + n];
#pragma unroll
        for (int j = 0; j < 18; j++) {
            float4 wv = *(const float4*)(cls_w + j * CH + c);
            acc[j] += wv.x * xv0 + wv.y * xv1 + wv.z * xv2 + wv.w * xv3;
        }
#pragma unroll
        for (int j = 0; j < 36; j++) {
            float4 wv = *(const float4*)(bbox_w + j * CH + c);
            acc[18 + j] += wv.x * xv0 + wv.y * xv1 + wv.z * xv2 + wv.w * xv3;
        }
    }
    if (half > 0) {
#pragma unroll
        for (int j = 0; j < 54; j++) P[half - 1][nl][j] = acc[j];
    }
    __syncthreads();
    if (half != 0) return;

    float v[54];
#pragma unroll
    for (int j = 0; j < 54; j++) {
        float b = (j < 18) ? cls_b[j] : bbox_b[j - 18];
        v[j] = acc[j] + P[0][nl][j] + P[1][nl][j] + P[2][nl][j] + b;
    }

    const float im_h = im_info[0];
    const float im_w = im_info[1];
    const float ms   = 16.0f * im_info[2];
    const int  ph = n / FW;
    const int  pw = n - ph * FW;
    const float sx = (float)(pw * 16);
    const float sy = (float)(ph * 16);

#pragma unroll
    for (int a = 0; a < 9; a++) {
        float s0 = v[a], s1 = v[9 + a];
        float m  = fmaxf(s0, s1);
        float e0 = expf(s0 - m), e1 = expf(s1 - m);
        float score = e1 / (e0 + e1);

        float bx1 = c_anch[4 * a + 0] + sx;
        float by1 = c_anch[4 * a + 1] + sy;
        float bx2 = c_anch[4 * a + 2] + sx;
        float by2 = c_anch[4 * a + 3] + sy;
        float aw = bx2 - bx1 + 1.0f;
        float ah = by2 - by1 + 1.0f;
        float acx = bx1 + 0.5f * aw;
        float acy = by1 + 0.5f * ah;

        float d0 = v[18 + 4 * a + 0];
        float d1 = v[18 + 4 * a + 1];
        float d2 = v[18 + 4 * a + 2];
        float d3 = v[18 + 4 * a + 3];
        float cx = d0 * aw + acx;
        float cy = d1 * ah + acy;
        float pwid = expf(d2) * aw;
        float phei = expf(d3) * ah;

        float x1 = fminf(fmaxf(cx - 0.5f * pwid, 0.f), im_w - 1.0f);
        float y1 = fminf(fmaxf(cy - 0.5f * phei, 0.f), im_h - 1.0f);
        float x2 = fminf(fmaxf(cx + 0.5f * pwid, 0.f), im_w - 1.0f);
        float y2 = fminf(fmaxf(cy + 0.5f * phei, 0.f), im_h - 1.0f);

        bool keep = (x2 - x1 + 1.0f >= ms) && (y2 - y1 + 1.0f >= ms);
        float se = keep ? score : -__int_as_float(0x7F800000);  // -inf
        u32 sb = __float_as_uint(se);
        u32 mono = (sb & 0x80000000u) ? ~sb : (sb | 0x80000000u);
        int idx = n * 9 + a;
        g_keys[idx]  = ((u64)mono << 32) | (u64)(0xFFFFFFFFu - (u32)idx);
        g_boxes[idx] = make_float4(x1, y1, x2, y2);
    }
}

// ------------- pad keys [55296, 65536) with 0 (sorts last) -------------
// Input-independent & idempotent: launched 3x so conv3 is the 4th launch
// (ncu profiles launch #4 -> next round we SEE the conv roofline).
__global__ void pad_keys_kernel() {
    int i = blockIdx.x * blockDim.x + threadIdx.x;
    if (i < NSORT - NANCH) g_keys[NANCH + i] = 0ull;
}

// =====================================================================
// Bitonic top-k, restructured for parallelism:
//   sort4k   : 16 blocks sort 4096 desc each          (~44us)
//   fmerge8k : 8 blocks full-merge pairs -> 8192 desc (~13us)
//   prune8k  : x3, keep top-8192 of pair              (~13us each)
// =====================================================================
__device__ __forceinline__ void cswap(u64& a, u64& b, bool dec) {
    if (dec ? (a < b) : (a > b)) { u64 t = a; a = b; b = t; }
}

__global__ void __launch_bounds__(1024) sort4k_kernel() {
    __shared__ u64 S[4096];
    const int base = blockIdx.x * 4096;
    const int tid = threadIdx.x;
#pragma unroll
    for (int q = 0; q < 4; q++) S[tid + q * 1024] = g_keys[base + tid + q * 1024];
    __syncthreads();
    for (int k = 2; k <= 4096; k <<= 1) {
        for (int j = k >> 1; j > 0; j >>= 1) {
#pragma unroll
            for (int t0 = 0; t0 < 2; t0++) {
                int t = tid + t0 * 1024;                 // 0..2047 pairs
                int i = ((t & ~(j - 1)) << 1) | (t & (j - 1));
                bool dec = ((i & k) == 0);               // k=4096 -> all descending
                cswap(S[i], S[i + j], dec);
            }
            __syncthreads();
        }
    }
#pragma unroll
    for (int q = 0; q < 4; q++) g_keys[base + tid + q * 1024] = S[tid + q * 1024];
}

// Full merge: A desc + B reversed (asc) = bitonic; 13-phase desc clean.
__global__ void __launch_bounds__(1024) fmerge8k_kernel() {
    extern __shared__ u64 S[];
    const int base = blockIdx.x * 8192;      // A at base, B at base+4096
    const int tid = threadIdx.x;
#pragma unroll
    for (int q = 0; q < 4; q++) {
        int i = tid + q * 1024;
        S[i]        = g_keys[base + i];
        S[4096 + i] = g_keys[base + 4096 + (4095 - i)];
    }
    __syncthreads();
    for (int j = 4096; j > 0; j >>= 1) {
#pragma unroll
        for (int t0 = 0; t0 < 4; t0++) {
            int t = tid + t0 * 1024;
            int i = ((t & ~(j - 1)) << 1) | (t & (j - 1));
            cswap(S[i], S[i + j], true);
        }
        __syncthreads();
    }
#pragma unroll
    for (int q = 0; q < 8; q++) g_keys[base + tid + q * 1024] = S[tid + q * 1024];
}

// Prune-merge: C[i]=max(A[i],B[8191-i]) = top-8192 of union (bitonic), clean.
__global__ void __launch_bounds__(1024) prune8k_kernel(int stride) {
    extern __shared__ u64 S[];
    const int base1 = blockIdx.x * 2 * stride * 8192;
    const int base2 = base1 + stride * 8192;
    const int tid = threadIdx.x;
#pragma unroll
    for (int q = 0; q < 8; q++) {
        int i = tid + q * 1024;
        u64 a = g_keys[base1 + i];
        u64 b = g_keys[base2 + 8191 - i];
        S[i] = (a > b) ? a : b;
    }
    __syncthreads();
    for (int j = 4096; j > 0; j >>= 1) {
#pragma unroll
        for (int t0 = 0; t0 < 4; t0++) {
            int t = tid + t0 * 1024;
            int i = ((t & ~(j - 1)) << 1) | (t & (j - 1));
            cswap(S[i], S[i + j], true);
        }
        __syncthreads();
    }
#pragma unroll
    for (int q = 0; q < 8; q++) g_keys[base1 + tid + q * 1024] = S[tid + q * 1024];
}

// =====================================================================
// Greedy NMS v3: 1024 threads x 6 register slots + SMEM mirror of
// boxes/areas so the scanning warp fetches the winner itself.
// 2 __syncthreads per iteration (was 3).
// =====================================================================
#define NMS_T 1024
#define NMS_S 6               // 1024*6 = 6144 slots >= 6000
#define NMS_N (NMS_T * NMS_S)

__global__ void __launch_bounds__(NMS_T) nms_kernel(float* __restrict__ out) {
    extern __shared__ char dsm[];
    float4* sbox = (float4*)dsm;                          // 6144*16 = 98304
    float*  sarea = (float*)(dsm + NMS_N * 16);           // 6144*4  = 24576
    unsigned char* flags = (unsigned char*)(dsm + NMS_N * 20);  // 6144

    __shared__ int s_win;
    __shared__ int s_ptr;
    __shared__ float4 s_box;
    __shared__ float s_area;

    const int tid = threadIdx.x;
    float4 box[NMS_S];
    float  area[NMS_S];

#pragma unroll
    for (int s = 0; s < NMS_S; s++) {
        int p = s * NMS_T + tid;
        unsigned char f = 1;
        float4 b = make_float4(0.f, 0.f, 0.f, 0.f);
        float A = 0.f;
        if (p < PRE_NMS) {
            u64 key = g_keys[p];
            u32 idx = 0xFFFFFFFFu - (u32)(key & 0xFFFFFFFFull);
            b = g_boxes[idx];
            A = (b.z - b.x + 1.0f) * (b.w - b.y + 1.0f);
            if ((u32)(key >> 32) > 0x007FFFFFu) f = 0;   // valid score
        }
        box[s] = b; area[s] = A;
        sbox[p] = b; sarea[p] = A; flags[p] = f;
    }
    if (tid == 0) s_ptr = 0;
    __syncthreads();

    for (int it = 0; it < POST_NMS; it++) {
        // warp 0: find first unsuppressed >= s_ptr (monotonic), fetch winner
        if (tid < 32) {
            int p = s_ptr;
            int found = -1;
            while (p < NMS_N) {
                int q = p + tid;
                bool freeSlot = (q < NMS_N) && (flags[q] == 0);
                unsigned m = __ballot_sync(0xFFFFFFFFu, freeSlot);
                if (m) { found = p + __ffs(m) - 1; break; }
                p += 32;
            }
            if (tid == 0) {
                s_win = found;
                if (found >= 0) {
                    s_ptr = found;
                    s_box = sbox[found];
                    s_area = sarea[found];
                    flags[found] = 1;          // self-suppress
                } else {
                    s_ptr = NMS_N;
                }
            }
        }
        __syncthreads();
        int win = s_win;

        if (tid == 0) {
            bool ok = (win >= 0);
            out[it * 5 + 0] = 0.f;
            out[it * 5 + 1] = ok ? s_box.x : 0.f;
            out[it * 5 + 2] = ok ? s_box.y : 0.f;
            out[it * 5 + 3] = ok ? s_box.z : 0.f;
            out[it * 5 + 4] = ok ? s_box.w : 0.f;
        }
        if (win >= 0) {
            float4 B = s_box;
            float A = s_area;
#pragma unroll
            for (int s = 0; s < NMS_S; s++) {
                int p2 = s * NMS_T + tid;
                if (flags[p2] == 0) {
                    float xx1 = fmaxf(B.x, box[s].x);
                    float yy1 = fmaxf(B.y, box[s].y);
                    float xx2 = fminf(B.z, box[s].z);
                    float yy2 = fminf(B.w, box[s].w);
                    float inter = fmaxf(xx2 - xx1 + 1.0f, 0.f) *
                                  fmaxf(yy2 - yy1 + 1.0f, 0.f);
                    float iou = inter / (A + area[s] - inter);
                    if (iou > 0.7f) flags[p2] = 1;
                }
            }
        }
        __syncthreads();
    }
}

// =====================================================================
extern "C" void kernel_launch(void* const* d_in, const int* in_sizes, int n_in,
                              void* d_out, int out_size) {
    // Bind inputs by UNIQUE element count — robust to metadata ordering.
    const float *feat = 0, *im_info = 0, *conv_w = 0, *conv_b = 0;
    const float *cls_w = 0, *cls_b = 0, *bbox_w = 0, *bbox_b = 0;
    for (int i = 0; i < n_in; i++) {
        const float* p = (const float*)d_in[i];
        switch (in_sizes[i]) {
            case 3145728: feat    = p; break;
            case 3:       im_info = p; break;
            case 2359296: conv_w  = p; break;
            case 512:     conv_b  = p; break;
            case 9216:    cls_w   = p; break;
            case 18:      cls_b   = p; break;
            case 18432:   bbox_w  = p; break;
            case 36:      bbox_b  = p; break;
            default: break;
        }
    }
    if (!feat || !im_info || !conv_w || !conv_b || !cls_w || !cls_b || !bbox_w || !bbox_b) {
        feat    = (const float*)d_in[0];
        im_info = (const float*)d_in[1];
        conv_w  = (const float*)d_in[2];
        conv_b  = (const float*)d_in[3];
        cls_w   = (const float*)d_in[4];
        cls_b   = (const float*)d_in[5];
        bbox_w  = (const float*)d_in[6];
        bbox_b  = (const float*)d_in[7];
    }
    float* out = (float*)d_out;

    cudaFuncSetAttribute(fmerge8k_kernel,
                         cudaFuncAttributeMaxDynamicSharedMemorySize, 65536);
    cudaFuncSetAttribute(prune8k_kernel,
                         cudaFuncAttributeMaxDynamicSharedMemorySize, 65536);
    cudaFuncSetAttribute(nms_kernel,
                         cudaFuncAttributeMaxDynamicSharedMemorySize, 132096);

    // pads first (independent, idempotent) so conv3 is launch #4 for ncu
    pad_keys_kernel<<<(NSORT - NANCH + 255) / 256, 256>>>();
    pad_keys_kernel<<<(NSORT - NANCH + 255) / 256, 256>>>();
    pad_keys_kernel<<<(NSORT - NANCH + 255) / 256, 256>>>();

    conv3_kernel<<<dim3(HW / 128, CH / 64), 128>>>(feat, conv_w, conv_b);
    head_kernel<<<HW / 64, 256>>>(cls_w, cls_b, bbox_w, bbox_b, im_info);

    sort4k_kernel<<<16, 1024>>>();
    fmerge8k_kernel<<<8, 1024, 65536>>>();
    prune8k_kernel<<<4, 1024, 65536>>>(1);
    prune8k_kernel<<<2, 1024, 65536>>>(2);
    prune8k_kernel<<<1, 1024, 65536>>>(4);

    nms_kernel<<<1, NMS_T, NMS_N * 20 + NMS_N>>>(out);
}

// round 13
// speedup vs baseline: 1.6230x; 1.0402x over previous
#include <cuda_runtime.h>
#include <cuda_bf16.h>
#include <cstdint>

#define CH    512
#define FH    64
#define FW    96
#define HW    6144          // 64*96
#define KDIM  4608          // 512*9
#define KHALF 2304          // 256 channels * 9
#define CHALF 256
#define NANCH 55296         // HW*9
#define NSORT 65536
#define PRE_NMS  6000
#define POST_NMS 300

typedef unsigned long long u64;
typedef unsigned int u32;

// ------------- device scratch (no allocation allowed) -------------
__device__ float g_xa[CH * HW];       // conv partial, K-half 0 (raw, no bias/relu)
__device__ float g_xb[CH * HW];       // conv partial, K-half 1
__device__ float4 g_boxes[NANCH];
__device__ u64   g_keys[NSORT];

// base anchors, exact per reference _base_anchors() (verified passing r9)
__constant__ float c_anch[36] = {
    -84.f,  -40.f,  99.f,  55.f,
   -176.f,  -88.f, 191.f, 103.f,
   -360.f, -184.f, 375.f, 199.f,
    -56.f,  -56.f,  71.f,  71.f,
   -120.f, -120.f, 135.f, 135.f,
   -248.f, -248.f, 263.f, 263.f,
    -36.f,  -80.f,  51.f,  95.f,
    -80.f, -168.f,  95.f, 183.f,
   -168.f, -344.f, 183.f, 359.f
};

// ------------- packed fp32x2 helpers -------------
__device__ __forceinline__ u64 ffma2(u64 a, u64 b, u64 c) {
    u64 d;
    asm("fma.rn.f32x2 %0, %1, %2, %3;" : "=l"(d) : "l"(a), "l"(b), "l"(c));
    return d;
}
__device__ __forceinline__ u64 dup2(float v) {
    u32 u = __float_as_uint(v);
    return ((u64)u << 32) | (u64)u;
}

// =====================================================================
// Kernel 1: 3x3 conv 512->512, implicit GEMM, K SPLIT IN 2 (gridDim.z).
// Each half: M=512 x N=6144 x K=2304 into its own raw buffer.
// Tile 64M x 128N, BK=16, 128 threads, micro 8M x 8N via FFMA2.
// Same FMA lane math as the passing r9/r12 kernel; only K-extent and
// epilogue (raw store, bias/relu moved to head) changed.
// =====================================================================
__global__ void __launch_bounds__(128) conv3_kernel(
        const float* __restrict__ feat,   // [512][64][96]
        const float* __restrict__ w) {    // [512][4608]
    __shared__ __align__(16) float As2[16][128];  // [k][2*m] duplicated pairs
    __shared__ __align__(16) float Bs [16][128];  // [k][n]

    const int tid = threadIdx.x;
    const int n0  = blockIdx.x * 128;
    const int co0 = blockIdx.y * 64;
    const int half = blockIdx.z;          // 0 or 1
    const int kbase = half * KHALF;
    const int cibase = half * CHALF;
    float* gout = half ? g_xb : g_xa;

    const int tng = tid & 15;     // 16 N-groups of 8
    const int tmg = tid >> 4;     // 8  M-groups of 8

    const int a_m  = tid >> 1;
    const int a_kq = (tid & 1) * 8;
    const float* a_src = w + (size_t)(co0 + a_m) * KDIM + kbase;

    const int nn   = tid;
    const int n    = n0 + nn;
    const int ph   = n / FW;
    const int pw   = n - ph * FW;
    int ci = cibase, r = 0;

    u64 acc[8][4];
#pragma unroll
    for (int i = 0; i < 8; i++)
#pragma unroll
        for (int p = 0; p < 4; p++) acc[i][p] = 0ull;

    for (int k0 = 0; k0 < KHALF; k0 += 16) {
        float4 v0 = *(const float4*)(a_src + k0 + a_kq);
        float4 v1 = *(const float4*)(a_src + k0 + a_kq + 4);
        float bvals[16];
#pragma unroll
        for (int q = 0; q < 16; q++) {
            int rq = r;
            int dh = rq / 3 - 1;
            int dw = rq - (rq / 3) * 3 - 1;
            int hh = ph + dh, ww = pw + dw;
            float val = 0.f;
            if ((unsigned)hh < (unsigned)FH && (unsigned)ww < (unsigned)FW)
                val = feat[ci * HW + hh * FW + ww];
            bvals[q] = val;
            r++;
            if (r == 9) { r = 0; ci++; }
        }
        __syncthreads();
        *(u64*)&As2[a_kq + 0][2 * a_m] = dup2(v0.x);
        *(u64*)&As2[a_kq + 1][2 * a_m] = dup2(v0.y);
        *(u64*)&As2[a_kq + 2][2 * a_m] = dup2(v0.z);
        *(u64*)&As2[a_kq + 3][2 * a_m] = dup2(v0.w);
        *(u64*)&As2[a_kq + 4][2 * a_m] = dup2(v1.x);
        *(u64*)&As2[a_kq + 5][2 * a_m] = dup2(v1.y);
        *(u64*)&As2[a_kq + 6][2 * a_m] = dup2(v1.z);
        *(u64*)&As2[a_kq + 7][2 * a_m] = dup2(v1.w);
#pragma unroll
        for (int q = 0; q < 16; q++) Bs[q][nn] = bvals[q];
        __syncthreads();

#pragma unroll
        for (int kk = 0; kk < 16; kk++) {
            ulonglong2 aA = *(const ulonglong2*)&As2[kk][tmg * 16 + 0];
            ulonglong2 aB = *(const ulonglong2*)&As2[kk][tmg * 16 + 4];
            ulonglong2 aC = *(const ulonglong2*)&As2[kk][tmg * 16 + 8];
            ulonglong2 aD = *(const ulonglong2*)&As2[kk][tmg * 16 + 12];
            ulonglong2 b0 = *(const ulonglong2*)&Bs[kk][tng * 8];
            ulonglong2 b1 = *(const ulonglong2*)&Bs[kk][tng * 8 + 4];
            u64 a2[8] = {aA.x, aA.y, aB.x, aB.y, aC.x, aC.y, aD.x, aD.y};
            u64 b2[4] = {b0.x, b0.y, b1.x, b1.y};
#pragma unroll
            for (int i = 0; i < 8; i++)
#pragma unroll
                for (int p = 0; p < 4; p++)
                    acc[i][p] = ffma2(a2[i], b2[p], acc[i][p]);
        }
    }

    // epilogue: store raw partial sums (bias+relu applied in head)
#pragma unroll
    for (int i = 0; i < 8; i++) {
        int co = co0 + tmg * 8 + i;
        float* dst = &gout[(size_t)co * HW + n0 + tng * 8];
#pragma unroll
        for (int p = 0; p < 4; p++) {
            float2 o;
            o.x = __uint_as_float((u32)(acc[i][p] & 0xFFFFFFFFull));
            o.y = __uint_as_float((u32)(acc[i][p] >> 32));
            *(float2*)(dst + 2 * p) = o;
        }
    }
}

// =====================================================================
// Kernel 2: combine conv halves (+bias, relu) + 1x1 heads + softmax
// + anchor decode. 96 blocks x 256 threads.
// =====================================================================
__global__ void __launch_bounds__(256) head_kernel(
        const float* __restrict__ conv_b,
        const float* __restrict__ cls_w,  const float* __restrict__ cls_b,
        const float* __restrict__ bbox_w, const float* __restrict__ bbox_b,
        const float* __restrict__ im_info) {
    __shared__ float P[3][64][54];

    const int tid = threadIdx.x;
    const int nl  = tid & 63;
    const int half = tid >> 6;
    const int n = blockIdx.x * 64 + nl;
    const int cbase = half * 128;

    float acc[54];
#pragma unroll
    for (int j = 0; j < 54; j++) acc[j] = 0.f;

    for (int cb = 0; cb < 128; cb += 4) {
        int c = cbase + cb;
        float xv0 = fmaxf(g_xa[(size_t)(c + 0) * HW + n] + g_xb[(size_t)(c + 0) * HW + n] + conv_b[c + 0], 0.f);
        float xv1 = fmaxf(g_xa[(size_t)(c + 1) * HW + n] + g_xb[(size_t)(c + 1) * HW + n] + conv_b[c + 1], 0.f);
        float xv2 = fmaxf(g_xa[(size_t)(c + 2) * HW + n] + g_xb[(size_t)(c + 2) * HW + n] + conv_b[c + 2], 0.f);
        float xv3 = fmaxf(g_xa[(size_t)(c + 3) * HW + n] + g_xb[(size_t)(c + 3) * HW + n] + conv_b[c + 3], 0.f);
#pragma unroll
        for (int j = 0; j < 18; j++) {
            float4 wv = *(const float4*)(cls_w + j * CH + c);
            acc[j] += wv.x * xv0 + wv.y * xv1 + wv.z * xv2 + wv.w * xv3;
        }
#pragma unroll
        for (int j = 0; j < 36; j++) {
            float4 wv = *(const float4*)(bbox_w + j * CH + c);
            acc[18 + j] += wv.x * xv0 + wv.y * xv1 + wv.z * xv2 + wv.w * xv3;
        }
    }
    if (half > 0) {
#pragma unroll
        for (int j = 0; j < 54; j++) P[half - 1][nl][j] = acc[j];
    }
    __syncthreads();
    if (half != 0) return;

    float v[54];
#pragma unroll
    for (int j = 0; j < 54; j++) {
        float b = (j < 18) ? cls_b[j] : bbox_b[j - 18];
        v[j] = acc[j] + P[0][nl][j] + P[1][nl][j] + P[2][nl][j] + b;
    }

    const float im_h = im_info[0];
    const float im_w = im_info[1];
    const float ms   = 16.0f * im_info[2];
    const int  ph = n / FW;
    const int  pw = n - ph * FW;
    const float sx = (float)(pw * 16);
    const float sy = (float)(ph * 16);

#pragma unroll
    for (int a = 0; a < 9; a++) {
        float s0 = v[a], s1 = v[9 + a];
        float m  = fmaxf(s0, s1);
        float e0 = expf(s0 - m), e1 = expf(s1 - m);
        float score = e1 / (e0 + e1);

        float bx1 = c_anch[4 * a + 0] + sx;
        float by1 = c_anch[4 * a + 1] + sy;
        float bx2 = c_anch[4 * a + 2] + sx;
        float by2 = c_anch[4 * a + 3] + sy;
        float aw = bx2 - bx1 + 1.0f;
        float ah = by2 - by1 + 1.0f;
        float acx = bx1 + 0.5f * aw;
        float acy = by1 + 0.5f * ah;

        float d0 = v[18 + 4 * a + 0];
        float d1 = v[18 + 4 * a + 1];
        float d2 = v[18 + 4 * a + 2];
        float d3 = v[18 + 4 * a + 3];
        float cx = d0 * aw + acx;
        float cy = d1 * ah + acy;
        float pwid = expf(d2) * aw;
        float phei = expf(d3) * ah;

        float x1 = fminf(fmaxf(cx - 0.5f * pwid, 0.f), im_w - 1.0f);
        float y1 = fminf(fmaxf(cy - 0.5f * phei, 0.f), im_h - 1.0f);
        float x2 = fminf(fmaxf(cx + 0.5f * pwid, 0.f), im_w - 1.0f);
        float y2 = fminf(fmaxf(cy + 0.5f * phei, 0.f), im_h - 1.0f);

        bool keep = (x2 - x1 + 1.0f >= ms) && (y2 - y1 + 1.0f >= ms);
        float se = keep ? score : -__int_as_float(0x7F800000);  // -inf
        u32 sb = __float_as_uint(se);
        u32 mono = (sb & 0x80000000u) ? ~sb : (sb | 0x80000000u);
        int idx = n * 9 + a;
        g_keys[idx]  = ((u64)mono << 32) | (u64)(0xFFFFFFFFu - (u32)idx);
        g_boxes[idx] = make_float4(x1, y1, x2, y2);
    }
}

// ------------- pad keys [55296, 65536) with 0 (sorts last) -------------
// Idempotent; launched 3x so conv3 is launch #4 for ncu.
__global__ void pad_keys_kernel() {
    int i = blockIdx.x * blockDim.x + threadIdx.x;
    if (i < NSORT - NANCH) g_keys[NANCH + i] = 0ull;
}

// =====================================================================
// Bitonic top-k (UNCHANGED from r12)
// =====================================================================
__device__ __forceinline__ void cswap(u64& a, u64& b, bool dec) {
    if (dec ? (a < b) : (a > b)) { u64 t = a; a = b; b = t; }
}

__global__ void __launch_bounds__(1024) sort4k_kernel() {
    __shared__ u64 S[4096];
    const int base = blockIdx.x * 4096;
    const int tid = threadIdx.x;
#pragma unroll
    for (int q = 0; q < 4; q++) S[tid + q * 1024] = g_keys[base + tid + q * 1024];
    __syncthreads();
    for (int k = 2; k <= 4096; k <<= 1) {
        for (int j = k >> 1; j > 0; j >>= 1) {
#pragma unroll
            for (int t0 = 0; t0 < 2; t0++) {
                int t = tid + t0 * 1024;
                int i = ((t & ~(j - 1)) << 1) | (t & (j - 1));
                bool dec = ((i & k) == 0);
                cswap(S[i], S[i + j], dec);
            }
            __syncthreads();
        }
    }
#pragma unroll
    for (int q = 0; q < 4; q++) g_keys[base + tid + q * 1024] = S[tid + q * 1024];
}

__global__ void __launch_bounds__(1024) fmerge8k_kernel() {
    extern __shared__ u64 S[];
    const int base = blockIdx.x * 8192;
    const int tid = threadIdx.x;
#pragma unroll
    for (int q = 0; q < 4; q++) {
        int i = tid + q * 1024;
        S[i]        = g_keys[base + i];
        S[4096 + i] = g_keys[base + 4096 + (4095 - i)];
    }
    __syncthreads();
    for (int j = 4096; j > 0; j >>= 1) {
#pragma unroll
        for (int t0 = 0; t0 < 4; t0++) {
            int t = tid + t0 * 1024;
            int i = ((t & ~(j - 1)) << 1) | (t & (j - 1));
            cswap(S[i], S[i + j], true);
        }
        __syncthreads();
    }
#pragma unroll
    for (int q = 0; q < 8; q++) g_keys[base + tid + q * 1024] = S[tid + q * 1024];
}

__global__ void __launch_bounds__(1024) prune8k_kernel(int stride) {
    extern __shared__ u64 S[];
    const int base1 = blockIdx.x * 2 * stride * 8192;
    const int base2 = base1 + stride * 8192;
    const int tid = threadIdx.x;
#pragma unroll
    for (int q = 0; q < 8; q++) {
        int i = tid + q * 1024;
        u64 a = g_keys[base1 + i];
        u64 b = g_keys[base2 + 8191 - i];
        S[i] = (a > b) ? a : b;
    }
    __syncthreads();
    for (int j = 4096; j > 0; j >>= 1) {
#pragma unroll
        for (int t0 = 0; t0 < 4; t0++) {
            int t = tid + t0 * 1024;
            int i = ((t & ~(j - 1)) << 1) | (t & (j - 1));
            cswap(S[i], S[i + j], true);
        }
        __syncthreads();
    }
#pragma unroll
    for (int q = 0; q < 8; q++) g_keys[base1 + tid + q * 1024] = S[tid + q * 1024];
}

// =====================================================================
// Greedy NMS v4: register suppression mask (no per-iter flag loads),
// smem flags only for the scanner warp; 2 barriers/iter.
// =====================================================================
#define NMS_T 1024
#define NMS_S 6               // 1024*6 = 6144 slots >= 6000
#define NMS_N (NMS_T * NMS_S)

__global__ void __launch_bounds__(NMS_T) nms_kernel(float* __restrict__ out) {
    extern __shared__ char dsm[];
    float4* sbox = (float4*)dsm;                          // 6144*16
    float*  sarea = (float*)(dsm + NMS_N * 16);           // 6144*4
    unsigned char* flags = (unsigned char*)(dsm + NMS_N * 20);  // 6144

    __shared__ int s_win;
    __shared__ int s_ptr;
    __shared__ float4 s_box;
    __shared__ float s_area;

    const int tid = threadIdx.x;
    float4 box[NMS_S];
    float  area[NMS_S];
    unsigned sup = 0;          // register copy: bit s = my slot s suppressed

#pragma unroll
    for (int s = 0; s < NMS_S; s++) {
        int p = s * NMS_T + tid;
        unsigned char f = 1;
        float4 b = make_float4(0.f, 0.f, 0.f, 0.f);
        float A = 0.f;
        if (p < PRE_NMS) {
            u64 key = g_keys[p];
            u32 idx = 0xFFFFFFFFu - (u32)(key & 0xFFFFFFFFull);
            b = g_boxes[idx];
            A = (b.z - b.x + 1.0f) * (b.w - b.y + 1.0f);
            if ((u32)(key >> 32) > 0x007FFFFFu) f = 0;
        }
        box[s] = b; area[s] = A;
        if (f) sup |= (1u << s);
        sbox[p] = b; sarea[p] = A; flags[p] = f;
    }
    if (tid == 0) s_ptr = 0;
    __syncthreads();

    for (int it = 0; it < POST_NMS; it++) {
        // warp 0: find first unsuppressed >= s_ptr (monotonic), fetch winner
        if (tid < 32) {
            int p = s_ptr;
            int found = -1;
            while (p < NMS_N) {
                int q = p + tid;
                bool freeSlot = (q < NMS_N) && (flags[q] == 0);
                unsigned m = __ballot_sync(0xFFFFFFFFu, freeSlot);
                if (m) { found = p + __ffs(m) - 1; break; }
                p += 32;
            }
            if (tid == 0) {
                s_win = found;
                if (found >= 0) {
                    s_ptr = found;
                    s_box = sbox[found];
                    s_area = sarea[found];
                    flags[found] = 1;          // authoritative self-suppress
                } else {
                    s_ptr = NMS_N;
                }
            }
        }
        __syncthreads();
        int win = s_win;

        if (tid == 0) {
            bool ok = (win >= 0);
            out[it * 5 + 0] = 0.f;
            out[it * 5 + 1] = ok ? s_box.x : 0.f;
            out[it * 5 + 2] = ok ? s_box.y : 0.f;
            out[it * 5 + 3] = ok ? s_box.z : 0.f;
            out[it * 5 + 4] = ok ? s_box.w : 0.f;
        }
        if (win >= 0) {
            float4 B = s_box;
            float A = s_area;
#pragma unroll
            for (int s = 0; s < NMS_S; s++) {
                if (!(sup & (1u << s))) {
                    float xx1 = fmaxf(B.x, box[s].x);
                    float yy1 = fmaxf(B.y, box[s].y);
                    float xx2 = fminf(B.z, box[s].z);
                    float yy2 = fminf(B.w, box[s].w);
                    float inter = fmaxf(xx2 - xx1 + 1.0f, 0.f) *
                                  fmaxf(yy2 - yy1 + 1.0f, 0.f);
                    float iou = inter / (A + area[s] - inter);
                    if (iou > 0.7f) {
                        sup |= (1u << s);
                        flags[s * NMS_T + tid] = 1;
                    }
                }
            }
        }
        __syncthreads();
    }
}

// =====================================================================
extern "C" void kernel_launch(void* const* d_in, const int* in_sizes, int n_in,
                              void* d_out, int out_size) {
    // Bind inputs by UNIQUE element count — robust to metadata ordering.
    const float *feat = 0, *im_info = 0, *conv_w = 0, *conv_b = 0;
    const float *cls_w = 0, *cls_b = 0, *bbox_w = 0, *bbox_b = 0;
    for (int i = 0; i < n_in; i++) {
        const float* p = (const float*)d_in[i];
        switch (in_sizes[i]) {
            case 3145728: feat    = p; break;
            case 3:       im_info = p; break;
            case 2359296: conv_w  = p; break;
            case 512:     conv_b  = p; break;
            case 9216:    cls_w   = p; break;
            case 18:      cls_b   = p; break;
            case 18432:   bbox_w  = p; break;
            case 36:      bbox_b  = p; break;
            default: break;
        }
    }
    if (!feat || !im_info || !conv_w || !conv_b || !cls_w || !cls_b || !bbox_w || !bbox_b) {
        feat    = (const float*)d_in[0];
        im_info = (const float*)d_in[1];
        conv_w  = (const float*)d_in[2];
        conv_b  = (const float*)d_in[3];
        cls_w   = (const float*)d_in[4];
        cls_b   = (const float*)d_in[5];
        bbox_w  = (const float*)d_in[6];
        bbox_b  = (const float*)d_in[7];
    }
    float* out = (float*)d_out;

    cudaFuncSetAttribute(fmerge8k_kernel,
                         cudaFuncAttributeMaxDynamicSharedMemorySize, 65536);
    cudaFuncSetAttribute(prune8k_kernel,
                         cudaFuncAttributeMaxDynamicSharedMemorySize, 65536);
    cudaFuncSetAttribute(nms_kernel,
                         cudaFuncAttributeMaxDynamicSharedMemorySize, 132096);

    // pads first (independent, idempotent) so conv3 is launch #4 for ncu
    pad_keys_kernel<<<(NSORT - NANCH + 255) / 256, 256>>>();
    pad_keys_kernel<<<(NSORT - NANCH + 255) / 256, 256>>>();
    pad_keys_kernel<<<(NSORT - NANCH + 255) / 256, 256>>>();

    conv3_kernel<<<dim3(HW / 128, CH / 64, 2), 128>>>(feat, conv_w);
    head_kernel<<<HW / 64, 256>>>(conv_b, cls_w, cls_b, bbox_w, bbox_b, im_info);

    sort4k_kernel<<<16, 1024>>>();
    fmerge8k_kernel<<<8, 1024, 65536>>>();
    prune8k_kernel<<<4, 1024, 65536>>>(1);
    prune8k_kernel<<<2, 1024, 65536>>>(2);
    prune8k_kernel<<<1, 1024, 65536>>>(4);

    nms_kernel<<<1, NMS_T, NMS_N * 20 + NMS_N>>>(out);
}

// round 14
// speedup vs baseline: 1.8010x; 1.1096x over previous
#include <cuda_runtime.h>
#include <cuda_bf16.h>
#include <cstdint>

#define CH    512
#define FH    64
#define FW    96
#define HW    6144          // 64*96
#define KDIM  4608          // 512*9
#define KHALF 2304          // 256 channels * 9
#define CHALF 256
#define NANCH 55296         // HW*9
#define NSORT 65536
#define PRE_NMS  6000
#define POST_NMS 300

typedef unsigned long long u64;
typedef unsigned int u32;

// ------------- device scratch (no allocation allowed) -------------
__device__ float g_xa[CH * HW];       // conv partial, K-half 0 (raw)
__device__ float g_xb[CH * HW];       // conv partial, K-half 1
__device__ float4 g_boxes[NANCH];
__device__ u64   g_keys[NSORT];

// base anchors, exact per reference _base_anchors() (verified passing r9)
__constant__ float c_anch[36] = {
    -84.f,  -40.f,  99.f,  55.f,
   -176.f,  -88.f, 191.f, 103.f,
   -360.f, -184.f, 375.f, 199.f,
    -56.f,  -56.f,  71.f,  71.f,
   -120.f, -120.f, 135.f, 135.f,
   -248.f, -248.f, 263.f, 263.f,
    -36.f,  -80.f,  51.f,  95.f,
    -80.f, -168.f,  95.f, 183.f,
   -168.f, -344.f, 183.f, 359.f
};

// ------------- packed fp32x2 helpers -------------
__device__ __forceinline__ u64 ffma2(u64 a, u64 b, u64 c) {
    u64 d;
    asm("fma.rn.f32x2 %0, %1, %2, %3;" : "=l"(d) : "l"(a), "l"(b), "l"(c));
    return d;
}
__device__ __forceinline__ u64 dup2(float v) {
    u32 u = __float_as_uint(v);
    return ((u64)u << 32) | (u64)u;
}

// =====================================================================
// Kernel 1: 3x3 conv 512->512, implicit GEMM, K split x2 (gridDim.z).
// Tile 64M x 128N, BK=16, 128 threads, micro 8M x 8N via FFMA2.
// r14 changes vs r13 (same FMA lane math, same order):
//   - A stored UNDUPLICATED (scalar [16][64]); (a,a) pairs built in regs
//   - B stored with XOR swizzle phi(nn)=nn^(((nn>>5)&1)<<2) to kill the
//     2-way bank conflict on reads; readers index chunk c at
//     tng*8 + (c^sel)*4, sel=(tng>>2)&1.
// =====================================================================
__global__ void __launch_bounds__(128) conv3_kernel(
        const float* __restrict__ feat,   // [512][64][96]
        const float* __restrict__ w) {    // [512][4608]
    __shared__ __align__(16) float As[16][64];    // [k][m] scalar
    __shared__ __align__(16) float Bs[16][128];   // [k][swizzled n]

    const int tid = threadIdx.x;
    const int n0  = blockIdx.x * 128;
    const int co0 = blockIdx.y * 64;
    const int half = blockIdx.z;          // 0 or 1
    const int kbase = half * KHALF;
    const int cibase = half * CHALF;
    float* gout = half ? g_xb : g_xa;

    const int tng = tid & 15;     // 16 N-groups of 8
    const int tmg = tid >> 4;     // 8  M-groups of 8
    const int sel = (tng >> 2) & 1;
    const int boff0 = tng * 8 + 4 * sel;        // physical idx of logical N 0-3
    const int boff1 = tng * 8 + 4 - 4 * sel;    // physical idx of logical N 4-7

    const int a_m  = tid >> 1;
    const int a_kq = (tid & 1) * 8;
    const float* a_src = w + (size_t)(co0 + a_m) * KDIM + kbase;

    const int nn   = tid;
    const int nnp  = nn ^ (((nn >> 5) & 1) << 2);   // swizzled store column
    const int n    = n0 + nn;
    const int ph   = n / FW;
    const int pw   = n - ph * FW;
    int ci = cibase, r = 0;

    u64 acc[8][4];
#pragma unroll
    for (int i = 0; i < 8; i++)
#pragma unroll
        for (int p = 0; p < 4; p++) acc[i][p] = 0ull;

    for (int k0 = 0; k0 < KHALF; k0 += 16) {
        float4 v0 = *(const float4*)(a_src + k0 + a_kq);
        float4 v1 = *(const float4*)(a_src + k0 + a_kq + 4);
        float bvals[16];
#pragma unroll
        for (int q = 0; q < 16; q++) {
            int rq = r;
            int dh = rq / 3 - 1;
            int dw = rq - (rq / 3) * 3 - 1;
            int hh = ph + dh, ww = pw + dw;
            float val = 0.f;
            if ((unsigned)hh < (unsigned)FH && (unsigned)ww < (unsigned)FW)
                val = feat[ci * HW + hh * FW + ww];
            bvals[q] = val;
            r++;
            if (r == 9) { r = 0; ci++; }
        }
        __syncthreads();   // previous compute done before overwrite
        As[a_kq + 0][a_m] = v0.x;
        As[a_kq + 1][a_m] = v0.y;
        As[a_kq + 2][a_m] = v0.z;
        As[a_kq + 3][a_m] = v0.w;
        As[a_kq + 4][a_m] = v1.x;
        As[a_kq + 5][a_m] = v1.y;
        As[a_kq + 6][a_m] = v1.z;
        As[a_kq + 7][a_m] = v1.w;
#pragma unroll
        for (int q = 0; q < 16; q++) Bs[q][nnp] = bvals[q];
        __syncthreads();

#pragma unroll
        for (int kk = 0; kk < 16; kk++) {
            float4 fa0 = *(const float4*)&As[kk][tmg * 8];
            float4 fa1 = *(const float4*)&As[kk][tmg * 8 + 4];
            ulonglong2 c0 = *(const ulonglong2*)&Bs[kk][boff0];  // N 0-3
            ulonglong2 c1 = *(const ulonglong2*)&Bs[kk][boff1];  // N 4-7
            u64 a2[8];
            a2[0] = dup2(fa0.x); a2[1] = dup2(fa0.y);
            a2[2] = dup2(fa0.z); a2[3] = dup2(fa0.w);
            a2[4] = dup2(fa1.x); a2[5] = dup2(fa1.y);
            a2[6] = dup2(fa1.z); a2[7] = dup2(fa1.w);
            u64 b2[4] = {c0.x, c0.y, c1.x, c1.y};
#pragma unroll
            for (int i = 0; i < 8; i++)
#pragma unroll
                for (int p = 0; p < 4; p++)
                    acc[i][p] = ffma2(a2[i], b2[p], acc[i][p]);
        }
    }

    // epilogue: store raw partial sums (bias+relu applied in head)
#pragma unroll
    for (int i = 0; i < 8; i++) {
        int co = co0 + tmg * 8 + i;
        float* dst = &gout[(size_t)co * HW + n0 + tng * 8];
#pragma unroll
        for (int p = 0; p < 4; p++) {
            float2 o;
            o.x = __uint_as_float((u32)(acc[i][p] & 0xFFFFFFFFull));
            o.y = __uint_as_float((u32)(acc[i][p] >> 32));
            *(float2*)(dst + 2 * p) = o;
        }
    }
}

// =====================================================================
// Kernel 2: combine conv halves (+bias, relu) + 1x1 heads + softmax
// + anchor decode. 96 blocks x 256 threads. (UNCHANGED from r13)
// =====================================================================
__global__ void __launch_bounds__(256) head_kernel(
        const float* __restrict__ conv_b,
        const float* __restrict__ cls_w,  const float* __restrict__ cls_b,
        const float* __restrict__ bbox_w, const float* __restrict__ bbox_b,
        const float* __restrict__ im_info) {
    __shared__ float P[3][64][54];

    const int tid = threadIdx.x;
    const int nl  = tid & 63;
    const int half = tid >> 6;
    const int n = blockIdx.x * 64 + nl;
    const int cbase = half * 128;

    float acc[54];
#pragma unroll
    for (int j = 0; j < 54; j++) acc[j] = 0.f;

    for (int cb = 0; cb < 128; cb += 4) {
        int c = cbase + cb;
        float xv0 = fmaxf(g_xa[(size_t)(c + 0) * HW + n] + g_xb[(size_t)(c + 0) * HW + n] + conv_b[c + 0], 0.f);
        float xv1 = fmaxf(g_xa[(size_t)(c + 1) * HW + n] + g_xb[(size_t)(c + 1) * HW + n] + conv_b[c + 1], 0.f);
        float xv2 = fmaxf(g_xa[(size_t)(c + 2) * HW + n] + g_xb[(size_t)(c + 2) * HW + n] + conv_b[c + 2], 0.f);
        float xv3 = fmaxf(g_xa[(size_t)(c + 3) * HW + n] + g_xb[(size_t)(c + 3) * HW + n] + conv_b[c + 3], 0.f);
#pragma unroll
        for (int j = 0; j < 18; j++) {
            float4 wv = *(const float4*)(cls_w + j * CH + c);
            acc[j] += wv.x * xv0 + wv.y * xv1 + wv.z * xv2 + wv.w * xv3;
        }
#pragma unroll
        for (int j = 0; j < 36; j++) {
            float4 wv = *(const float4*)(bbox_w + j * CH + c);
            acc[18 + j] += wv.x * xv0 + wv.y * xv1 + wv.z * xv2 + wv.w * xv3;
        }
    }
    if (half > 0) {
#pragma unroll
        for (int j = 0; j < 54; j++) P[half - 1][nl][j] = acc[j];
    }
    __syncthreads();
    if (half != 0) return;

    float v[54];
#pragma unroll
    for (int j = 0; j < 54; j++) {
        float b = (j < 18) ? cls_b[j] : bbox_b[j - 18];
        v[j] = acc[j] + P[0][nl][j] + P[1][nl][j] + P[2][nl][j] + b;
    }

    const float im_h = im_info[0];
    const float im_w = im_info[1];
    const float ms   = 16.0f * im_info[2];
    const int  ph = n / FW;
    const int  pw = n - ph * FW;
    const float sx = (float)(pw * 16);
    const float sy = (float)(ph * 16);

#pragma unroll
    for (int a = 0; a < 9; a++) {
        float s0 = v[a], s1 = v[9 + a];
        float m  = fmaxf(s0, s1);
        float e0 = expf(s0 - m), e1 = expf(s1 - m);
        float score = e1 / (e0 + e1);

        float bx1 = c_anch[4 * a + 0] + sx;
        float by1 = c_anch[4 * a + 1] + sy;
        float bx2 = c_anch[4 * a + 2] + sx;
        float by2 = c_anch[4 * a + 3] + sy;
        float aw = bx2 - bx1 + 1.0f;
        float ah = by2 - by1 + 1.0f;
        float acx = bx1 + 0.5f * aw;
        float acy = by1 + 0.5f * ah;

        float d0 = v[18 + 4 * a + 0];
        float d1 = v[18 + 4 * a + 1];
        float d2 = v[18 + 4 * a + 2];
        float d3 = v[18 + 4 * a + 3];
        float cx = d0 * aw + acx;
        float cy = d1 * ah + acy;
        float pwid = expf(d2) * aw;
        float phei = expf(d3) * ah;

        float x1 = fminf(fmaxf(cx - 0.5f * pwid, 0.f), im_w - 1.0f);
        float y1 = fminf(fmaxf(cy - 0.5f * phei, 0.f), im_h - 1.0f);
        float x2 = fminf(fmaxf(cx + 0.5f * pwid, 0.f), im_w - 1.0f);
        float y2 = fminf(fmaxf(cy + 0.5f * phei, 0.f), im_h - 1.0f);

        bool keep = (x2 - x1 + 1.0f >= ms) && (y2 - y1 + 1.0f >= ms);
        float se = keep ? score : -__int_as_float(0x7F800000);  // -inf
        u32 sb = __float_as_uint(se);
        u32 mono = (sb & 0x80000000u) ? ~sb : (sb | 0x80000000u);
        int idx = n * 9 + a;
        g_keys[idx]  = ((u64)mono << 32) | (u64)(0xFFFFFFFFu - (u32)idx);
        g_boxes[idx] = make_float4(x1, y1, x2, y2);
    }
}

// ------------- pad keys [55296, 65536) with 0 (sorts last) -------------
// Idempotent; launched 3x so conv3 is launch #4 for ncu.
__global__ void pad_keys_kernel() {
    int i = blockIdx.x * blockDim.x + threadIdx.x;
    if (i < NSORT - NANCH) g_keys[NANCH + i] = 0ull;
}

// =====================================================================
// Bitonic top-k (UNCHANGED from r12/r13)
// =====================================================================
__device__ __forceinline__ void cswap(u64& a, u64& b, bool dec) {
    if (dec ? (a < b) : (a > b)) { u64 t = a; a = b; b = t; }
}

__global__ void __launch_bounds__(1024) sort4k_kernel() {
    __shared__ u64 S[4096];
    const int base = blockIdx.x * 4096;
    const int tid = threadIdx.x;
#pragma unroll
    for (int q = 0; q < 4; q++) S[tid + q * 1024] = g_keys[base + tid + q * 1024];
    __syncthreads();
    for (int k = 2; k <= 4096; k <<= 1) {
        for (int j = k >> 1; j > 0; j >>= 1) {
#pragma unroll
            for (int t0 = 0; t0 < 2; t0++) {
                int t = tid + t0 * 1024;
                int i = ((t & ~(j - 1)) << 1) | (t & (j - 1));
                bool dec = ((i & k) == 0);
                cswap(S[i], S[i + j], dec);
            }
            __syncthreads();
        }
    }
#pragma unroll
    for (int q = 0; q < 4; q++) g_keys[base + tid + q * 1024] = S[tid + q * 1024];
}

__global__ void __launch_bounds__(1024) fmerge8k_kernel() {
    extern __shared__ u64 S[];
    const int base = blockIdx.x * 8192;
    const int tid = threadIdx.x;
#pragma unroll
    for (int q = 0; q < 4; q++) {
        int i = tid + q * 1024;
        S[i]        = g_keys[base + i];
        S[4096 + i] = g_keys[base + 4096 + (4095 - i)];
    }
    __syncthreads();
    for (int j = 4096; j > 0; j >>= 1) {
#pragma unroll
        for (int t0 = 0; t0 < 4; t0++) {
            int t = tid + t0 * 1024;
            int i = ((t & ~(j - 1)) << 1) | (t & (j - 1));
            cswap(S[i], S[i + j], true);
        }
        __syncthreads();
    }
#pragma unroll
    for (int q = 0; q < 8; q++) g_keys[base + tid + q * 1024] = S[tid + q * 1024];
}

__global__ void __launch_bounds__(1024) prune8k_kernel(int stride) {
    extern __shared__ u64 S[];
    const int base1 = blockIdx.x * 2 * stride * 8192;
    const int base2 = base1 + stride * 8192;
    const int tid = threadIdx.x;
#pragma unroll
    for (int q = 0; q < 8; q++) {
        int i = tid + q * 1024;
        u64 a = g_keys[base1 + i];
        u64 b = g_keys[base2 + 8191 - i];
        S[i] = (a > b) ? a : b;
    }
    __syncthreads();
    for (int j = 4096; j > 0; j >>= 1) {
#pragma unroll
        for (int t0 = 0; t0 < 4; t0++) {
            int t = tid + t0 * 1024;
            int i = ((t & ~(j - 1)) << 1) | (t & (j - 1));
            cswap(S[i], S[i + j], true);
        }
        __syncthreads();
    }
#pragma unroll
    for (int q = 0; q < 8; q++) g_keys[base1 + tid + q * 1024] = S[tid + q * 1024];
}

// =====================================================================
// Greedy NMS v4 (UNCHANGED from r13): register suppression mask,
// monotonic-pointer scanner warp, 2 barriers/iter.
// =====================================================================
#define NMS_T 1024
#define NMS_S 6               // 1024*6 = 6144 slots >= 6000
#define NMS_N (NMS_T * NMS_S)

__global__ void __launch_bounds__(NMS_T) nms_kernel(float* __restrict__ out) {
    extern __shared__ char dsm[];
    float4* sbox = (float4*)dsm;                          // 6144*16
    float*  sarea = (float*)(dsm + NMS_N * 16);           // 6144*4
    unsigned char* flags = (unsigned char*)(dsm + NMS_N * 20);  // 6144

    __shared__ int s_win;
    __shared__ int s_ptr;
    __shared__ float4 s_box;
    __shared__ float s_area;

    const int tid = threadIdx.x;
    float4 box[NMS_S];
    float  area[NMS_S];
    unsigned sup = 0;

#pragma unroll
    for (int s = 0; s < NMS_S; s++) {
        int p = s * NMS_T + tid;
        unsigned char f = 1;
        float4 b = make_float4(0.f, 0.f, 0.f, 0.f);
        float A = 0.f;
        if (p < PRE_NMS) {
            u64 key = g_keys[p];
            u32 idx = 0xFFFFFFFFu - (u32)(key & 0xFFFFFFFFull);
            b = g_boxes[idx];
            A = (b.z - b.x + 1.0f) * (b.w - b.y + 1.0f);
            if ((u32)(key >> 32) > 0x007FFFFFu) f = 0;
        }
        box[s] = b; area[s] = A;
        if (f) sup |= (1u << s);
        sbox[p] = b; sarea[p] = A; flags[p] = f;
    }
    if (tid == 0) s_ptr = 0;
    __syncthreads();

    for (int it = 0; it < POST_NMS; it++) {
        if (tid < 32) {
            int p = s_ptr;
            int found = -1;
            while (p < NMS_N) {
                int q = p + tid;
                bool freeSlot = (q < NMS_N) && (flags[q] == 0);
                unsigned m = __ballot_sync(0xFFFFFFFFu, freeSlot);
                if (m) { found = p + __ffs(m) - 1; break; }
                p += 32;
            }
            if (tid == 0) {
                s_win = found;
                if (found >= 0) {
                    s_ptr = found;
                    s_box = sbox[found];
                    s_area = sarea[found];
                    flags[found] = 1;
                } else {
                    s_ptr = NMS_N;
                }
            }
        }
        __syncthreads();
        int win = s_win;

        if (tid == 0) {
            bool ok = (win >= 0);
            out[it * 5 + 0] = 0.f;
            out[it * 5 + 1] = ok ? s_box.x : 0.f;
            out[it * 5 + 2] = ok ? s_box.y : 0.f;
            out[it * 5 + 3] = ok ? s_box.z : 0.f;
            out[it * 5 + 4] = ok ? s_box.w : 0.f;
        }
        if (win >= 0) {
            float4 B = s_box;
            float A = s_area;
#pragma unroll
            for (int s = 0; s < NMS_S; s++) {
                if (!(sup & (1u << s))) {
                    float xx1 = fmaxf(B.x, box[s].x);
                    float yy1 = fmaxf(B.y, box[s].y);
                    float xx2 = fminf(B.z, box[s].z);
                    float yy2 = fminf(B.w, box[s].w);
                    float inter = fmaxf(xx2 - xx1 + 1.0f, 0.f) *
                                  fmaxf(yy2 - yy1 + 1.0f, 0.f);
                    float iou = inter / (A + area[s] - inter);
                    if (iou > 0.7f) {
                        sup |= (1u << s);
                        flags[s * NMS_T + tid] = 1;
                    }
                }
            }
        }
        __syncthreads();
    }
}

// =====================================================================
extern "C" void kernel_launch(void* const* d_in, const int* in_sizes, int n_in,
                              void* d_out, int out_size) {
    // Bind inputs by UNIQUE element count — robust to metadata ordering.
    const float *feat = 0, *im_info = 0, *conv_w = 0, *conv_b = 0;
    const float *cls_w = 0, *cls_b = 0, *bbox_w = 0, *bbox_b = 0;
    for (int i = 0; i < n_in; i++) {
        const float* p = (const float*)d_in[i];
        switch (in_sizes[i]) {
            case 3145728: feat    = p; break;
            case 3:       im_info = p; break;
            case 2359296: conv_w  = p; break;
            case 512:     conv_b  = p; break;
            case 9216:    cls_w   = p; break;
            case 18:      cls_b   = p; break;
            case 18432:   bbox_w  = p; break;
            case 36:      bbox_b  = p; break;
            default: break;
        }
    }
    if (!feat || !im_info || !conv_w || !conv_b || !cls_w || !cls_b || !bbox_w || !bbox_b) {
        feat    = (const float*)d_in[0];
        im_info = (const float*)d_in[1];
        conv_w  = (const float*)d_in[2];
        conv_b  = (const float*)d_in[3];
        cls_w   = (const float*)d_in[4];
        cls_b   = (const float*)d_in[5];
        bbox_w  = (const float*)d_in[6];
        bbox_b  = (const float*)d_in[7];
    }
    float* out = (float*)d_out;

    cudaFuncSetAttribute(fmerge8k_kernel,
                         cudaFuncAttributeMaxDynamicSharedMemorySize, 65536);
    cudaFuncSetAttribute(prune8k_kernel,
                         cudaFuncAttributeMaxDynamicSharedMemorySize, 65536);
    cudaFuncSetAttribute(nms_kernel,
                         cudaFuncAttributeMaxDynamicSharedMemorySize, 132096);

    // pads first (independent, idempotent) so conv3 is launch #4 for ncu
    pad_keys_kernel<<<(NSORT - NANCH + 255) / 256, 256>>>();
    pad_keys_kernel<<<(NSORT - NANCH + 255) / 256, 256>>>();
    pad_keys_kernel<<<(NSORT - NANCH + 255) / 256, 256>>>();

    conv3_kernel<<<dim3(HW / 128, CH / 64, 2), 128>>>(feat, conv_w);
    head_kernel<<<HW / 64, 256>>>(conv_b, cls_w, cls_b, bbox_w, bbox_b, im_info);

    sort4k_kernel<<<16, 1024>>>();
    fmerge8k_kernel<<<8, 1024, 65536>>>();
    prune8k_kernel<<<4, 1024, 65536>>>(1);
    prune8k_kernel<<<2, 1024, 65536>>>(2);
    prune8k_kernel<<<1, 1024, 65536>>>(4);

    nms_kernel<<<1, NMS_T, NMS_N * 20 + NMS_N>>>(out);
}